// round 1
// baseline (speedup 1.0000x reference)
#include <cuda_runtime.h>
#include <cuda_bf16.h>
#include <cstdint>

// ---------------- problem constants ----------------
#define BS   2
#define NQ   21760
#define EMBED 256
#define NH   8
#define NL   4
#define NP   4
#define HD   32
#define MROWS (BS * NQ)   // 43520

// level shapes {128,64,32,16} squares; starts in token space
__device__ __constant__ int c_dim[4]   = {128, 64, 32, 16};
__device__ __constant__ int c_start[4] = {0, 16384, 20480, 21504};

// ---------------- scratch (device globals; no allocation allowed) ----------
__device__ float g_v[MROWS * EMBED];      // projected value  [bs*V, 256]
__device__ float g_off[MROWS * EMBED];    // offsets          [bs*nq, 256]
__device__ float g_aw[MROWS * 128];       // attn logits      [bs*nq, 128]
__device__ float g_samp[MROWS * EMBED];   // sampled output   [bs*nq, 256]

// ---------------- fp32 tiled GEMM:  C[M,N] = A[M,K] @ B[K,N] + bias[N] ------
// BM=BN=64, BK=16, 256 threads, each computes 4x4.
// Requires M%64==0, N%64==0, K%16==0 (true for all our shapes).
__global__ void sgemm64(const float* __restrict__ A,
                        const float* __restrict__ B,
                        const float* __restrict__ bias,
                        float* __restrict__ C,
                        int M, int N, int K)
{
    __shared__ float As[16][64];
    __shared__ float Bs[16][64];

    const int tid = threadIdx.x;
    const int tx = tid & 15;        // 0..15 -> col group
    const int ty = tid >> 4;        // 0..15 -> row group
    const int m0 = blockIdx.y * 64;
    const int n0 = blockIdx.x * 64;

    // A-tile load map: 64 rows x 16 cols, each thread a float4 along K
    const int ar = tid >> 2;           // 0..63
    const int ac = (tid & 3) * 4;      // 0,4,8,12
    // B-tile load map: 16 rows x 64 cols, each thread a float4 along N
    const int br = tid >> 4;           // 0..15
    const int bc = (tid & 15) * 4;     // 0..60

    float acc[4][4];
#pragma unroll
    for (int i = 0; i < 4; i++)
#pragma unroll
        for (int j = 0; j < 4; j++) acc[i][j] = 0.f;

    for (int k0 = 0; k0 < K; k0 += 16) {
        float4 a4 = *(const float4*)(A + (size_t)(m0 + ar) * K + k0 + ac);
        As[ac + 0][ar] = a4.x;
        As[ac + 1][ar] = a4.y;
        As[ac + 2][ar] = a4.z;
        As[ac + 3][ar] = a4.w;
        *(float4*)(&Bs[br][bc]) =
            *(const float4*)(B + (size_t)(k0 + br) * N + n0 + bc);
        __syncthreads();

#pragma unroll
        for (int k = 0; k < 16; k++) {
            float4 av = *(const float4*)(&As[k][ty * 4]);
            float4 bv = *(const float4*)(&Bs[k][tx * 4]);
            float a[4] = {av.x, av.y, av.z, av.w};
            float b[4] = {bv.x, bv.y, bv.z, bv.w};
#pragma unroll
            for (int i = 0; i < 4; i++)
#pragma unroll
                for (int j = 0; j < 4; j++)
                    acc[i][j] = fmaf(a[i], b[j], acc[i][j]);
        }
        __syncthreads();
    }

    const int colBase = n0 + tx * 4;
    float4 bia = *(const float4*)(bias + colBase);
    float bb[4] = {bia.x, bia.y, bia.z, bia.w};
#pragma unroll
    for (int i = 0; i < 4; i++) {
        const int row = m0 + ty * 4 + i;
        float4 o;
        o.x = acc[i][0] + bb[0];
        o.y = acc[i][1] + bb[1];
        o.z = acc[i][2] + bb[2];
        o.w = acc[i][3] + bb[3];
        *(float4*)(C + (size_t)row * N + colBase) = o;
    }
}

// ---------------- fused softmax + deformable bilinear sampling --------------
// One warp per (b, q, h). lane == channel (HD=32). Lanes 0..15 (mirrored to
// 16..31) each own one (l,p) sample: compute softmax weight + pixel coords,
// then broadcast each sample to the whole warp for the coalesced gather.
__global__ void deform_sample(const float* __restrict__ ref,   // [bs,nq,4,2]
                              const float* __restrict__ off,   // [bs*nq,256]
                              const float* __restrict__ awr,   // [bs*nq,128]
                              const float* __restrict__ v,     // [bs*V,256]
                              float* __restrict__ out)         // [bs*nq,256]
{
    const int gw = (blockIdx.x * blockDim.x + threadIdx.x) >> 5;
    const int lane = threadIdx.x & 31;
    if (gw >= MROWS * NH) return;

    const int h = gw & (NH - 1);
    const int bq = gw >> 3;           // b*NQ + q
    const int b = bq / NQ;

    const int s = lane & 15;          // sample id (l*4+p), duplicated in hi half
    const int l = s >> 2;

    // softmax over 16 attn logits for this (b,q,h)
    float a = awr[(size_t)bq * 128 + h * 16 + s];
    float m = a;
#pragma unroll
    for (int o = 8; o; o >>= 1) m = fmaxf(m, __shfl_xor_sync(0xffffffffu, m, o));
    float e = expf(a - m);
    float sum = e;
#pragma unroll
    for (int o = 8; o; o >>= 1) sum += __shfl_xor_sync(0xffffffffu, sum, o);
    const float w = e / sum;

    // sample pixel coordinates:  x = ref_x*W + off_x - 0.5  (algebraic collapse
    // of the grid_sample align_corners=False convention)
    const int dim = c_dim[l];
    const float offx = off[(size_t)bq * 256 + (h * 16 + s) * 2 + 0];
    const float offy = off[(size_t)bq * 256 + (h * 16 + s) * 2 + 1];
    const float rx = ref[((size_t)bq * 4 + l) * 2 + 0];
    const float ry = ref[((size_t)bq * 4 + l) * 2 + 1];
    const float xs = rx * (float)dim + offx - 0.5f;
    const float ys = ry * (float)dim + offy - 0.5f;

    // channel pointer: v row = b*V + tok, element = h*32 + lane
    const float* vb = v + (size_t)b * NQ * EMBED + h * HD + lane;

    float acc = 0.f;
#pragma unroll
    for (int t = 0; t < 16; t++) {
        const float xt = __shfl_sync(0xffffffffu, xs, t);
        const float yt = __shfl_sync(0xffffffffu, ys, t);
        const float wt = __shfl_sync(0xffffffffu, w, t);
        const int li = t >> 2;
        const int W = c_dim[li];
        const int st = c_start[li];

        const float xf = floorf(xt), yf = floorf(yt);
        const int x0 = (int)xf, y0 = (int)yf;
        const float fx = xt - xf, fy = yt - yf;

        const bool x0i = (unsigned)x0 < (unsigned)W;
        const bool x1i = (unsigned)(x0 + 1) < (unsigned)W;
        const bool y0i = (unsigned)y0 < (unsigned)W;   // H==W (square levels)
        const bool y1i = (unsigned)(y0 + 1) < (unsigned)W;

        float v00 = 0.f, v01 = 0.f, v10 = 0.f, v11 = 0.f;
        const float* row0 = vb + ((size_t)st + (size_t)y0 * W) * EMBED;
        const float* row1 = row0 + (size_t)W * EMBED;
        if (y0i) {
            if (x0i) v00 = row0[(size_t)x0 * EMBED];
            if (x1i) v01 = row0[(size_t)x0 * EMBED + EMBED];
        }
        if (y1i) {
            if (x0i) v10 = row1[(size_t)x0 * EMBED];
            if (x1i) v11 = row1[(size_t)x0 * EMBED + EMBED];
        }
        const float top = v00 * (1.f - fx) + v01 * fx;
        const float bot = v10 * (1.f - fx) + v11 * fx;
        acc = fmaf(wt, top * (1.f - fy) + bot * fy, acc);
    }

    out[(size_t)bq * EMBED + h * HD + lane] = acc;
}

// ---------------- launch -----------------------------------------------------
extern "C" void kernel_launch(void* const* d_in, const int* in_sizes, int n_in,
                              void* d_out, int out_size)
{
    const float* query  = (const float*)d_in[0];   // [2,21760,256]
    const float* refpts = (const float*)d_in[1];   // [2,21760,4,2]
    const float* value  = (const float*)d_in[2];   // [2,21760,256]
    const float* W_off  = (const float*)d_in[3];   // [256,256]
    const float* b_off  = (const float*)d_in[4];   // [256]
    const float* W_attn = (const float*)d_in[5];   // [256,128]
    const float* b_attn = (const float*)d_in[6];   // [128]
    const float* W_v    = (const float*)d_in[7];   // [256,256]
    const float* b_v    = (const float*)d_in[8];   // [256]
    const float* W_out  = (const float*)d_in[9];   // [256,256]
    const float* b_out  = (const float*)d_in[10];  // [256]
    float* out = (float*)d_out;                    // [2,21760,256]

    float *v_s, *off_s, *aw_s, *samp_s;
    cudaGetSymbolAddress((void**)&v_s,    g_v);
    cudaGetSymbolAddress((void**)&off_s,  g_off);
    cudaGetSymbolAddress((void**)&aw_s,   g_aw);
    cudaGetSymbolAddress((void**)&samp_s, g_samp);

    const dim3 blk(256);
    const dim3 grid256(EMBED / 64, MROWS / 64);   // N=256
    const dim3 grid128(128 / 64,  MROWS / 64);    // N=128

    // 1) offsets = query @ W_off + b_off
    sgemm64<<<grid256, blk>>>(query, W_off, b_off, off_s, MROWS, 256, 256);
    // 2) attn logits = query @ W_attn + b_attn
    sgemm64<<<grid128, blk>>>(query, W_attn, b_attn, aw_s, MROWS, 128, 256);
    // 3) v = value @ W_v + b_v
    sgemm64<<<grid256, blk>>>(value, W_v, b_v, v_s, MROWS, 256, 256);
    // 4) fused softmax + deformable sampling
    {
        const int warps = MROWS * NH;               // 348160
        const int threads = 256;
        const int blocks = (warps * 32 + threads - 1) / threads;
        deform_sample<<<blocks, threads>>>(refpts, off_s, aw_s, v_s, samp_s);
    }
    // 5) out = samp @ W_out + b_out
    sgemm64<<<grid256, blk>>>(samp_s, W_out, b_out, out, MROWS, 256, 256);
}

// round 2
// speedup vs baseline: 1.8779x; 1.8779x over previous
#include <cuda_runtime.h>
#include <cuda_bf16.h>
#include <cstdint>

// ---------------- problem constants ----------------
#define BS   2
#define NQ   21760
#define EMBED 256
#define NH   8
#define HD   32
#define MROWS (BS * NQ)   // 43520

__device__ __constant__ int c_dim[4]   = {128, 64, 32, 16};
__device__ __constant__ int c_start[4] = {0, 16384, 20480, 21504};

// ---------------- scratch ----------------
__device__ float g_v[MROWS * EMBED];
__device__ float g_off[MROWS * EMBED];
__device__ float g_aw[MROWS * 128];
__device__ float g_samp[MROWS * EMBED];

// ---------------- TF32 tensor-core GEMM ----------------
// C[M,N] = A[M,K] @ B[K,N] + bias[N].  BM=128, BN=64, BK=16, 256 thr (8 warps).
// Warp grid 4x2 (M x N), warp tile 32x32 via m16n8k8 (2 m-tiles x 4 n-tiles).
__device__ __forceinline__ uint32_t f2tf32(float x) {
    uint32_t r;
    asm("cvt.rna.tf32.f32 %0, %1;" : "=r"(r) : "f"(x));
    return r;
}

__device__ __forceinline__ void mma_tf32(float* d, const uint32_t* a,
                                         const uint32_t* b) {
    asm volatile(
        "mma.sync.aligned.m16n8k8.row.col.f32.tf32.tf32.f32 "
        "{%0,%1,%2,%3}, {%4,%5,%6,%7}, {%8,%9}, {%0,%1,%2,%3};"
        : "+f"(d[0]), "+f"(d[1]), "+f"(d[2]), "+f"(d[3])
        : "r"(a[0]), "r"(a[1]), "r"(a[2]), "r"(a[3]), "r"(b[0]), "r"(b[1]));
}

#define AS_STRIDE 20   // 16 + 4 pad: stride%32==20 -> conflict-free frag loads
#define BS_STRIDE 68   // 64 + 4 pad: stride%32==4  -> conflict-free frag loads

__global__ __launch_bounds__(256) void tgemm_tf32(
    const float* __restrict__ A, const float* __restrict__ B,
    const float* __restrict__ bias, float* __restrict__ C,
    int M, int N, int K)
{
    __shared__ uint32_t As[2][128][AS_STRIDE];
    __shared__ uint32_t Bsm[2][16][BS_STRIDE];

    const int tid  = threadIdx.x;
    const int lane = tid & 31;
    const int wid  = tid >> 5;
    const int wm   = wid & 3;        // 0..3 -> 32-row group
    const int wn   = wid >> 2;       // 0..1 -> 32-col group
    const int t4   = lane >> 2;      // 0..7
    const int tq   = lane & 3;       // 0..3

    const int m0g = blockIdx.y * 128;
    const int n0g = blockIdx.x * 64;

    // global->reg staging maps
    // A: 128x16 tile = 512 float4; thread loads 2 (idx = tid, tid+256)
    const int ar0 = tid >> 2;              // rows for idx=tid
    const int ac0 = (tid & 3) * 4;
    const int ar1 = (tid + 256) >> 2;
    const int ac1 = ac0;                   // same col pattern
    // B: 16x64 tile = 256 float4; thread loads 1
    const int br = tid >> 4;
    const int bc = (tid & 15) * 4;

    float acc[2][4][4];
#pragma unroll
    for (int i = 0; i < 2; i++)
#pragma unroll
        for (int j = 0; j < 4; j++)
#pragma unroll
            for (int k = 0; k < 4; k++) acc[i][j][k] = 0.f;

    float4 a0r, a1r, b0r;
    const int S = K / 16;

    // prologue: load step 0
    a0r = *(const float4*)(A + (size_t)(m0g + ar0) * K + ac0);
    a1r = *(const float4*)(A + (size_t)(m0g + ar1) * K + ac1);
    b0r = *(const float4*)(B + (size_t)br * N + n0g + bc);

    {   // store to buf 0
        uint4 ua = {f2tf32(a0r.x), f2tf32(a0r.y), f2tf32(a0r.z), f2tf32(a0r.w)};
        *(uint4*)(&As[0][ar0][ac0]) = ua;
        uint4 ub = {f2tf32(a1r.x), f2tf32(a1r.y), f2tf32(a1r.z), f2tf32(a1r.w)};
        *(uint4*)(&As[0][ar1][ac1]) = ub;
        uint4 uc = {f2tf32(b0r.x), f2tf32(b0r.y), f2tf32(b0r.z), f2tf32(b0r.w)};
        *(uint4*)(&Bsm[0][br][bc]) = uc;
    }
    __syncthreads();

    for (int s = 0; s < S; s++) {
        const int buf = s & 1;
        if (s + 1 < S) {
            const int k0 = (s + 1) * 16;
            a0r = *(const float4*)(A + (size_t)(m0g + ar0) * K + k0 + ac0);
            a1r = *(const float4*)(A + (size_t)(m0g + ar1) * K + k0 + ac1);
            b0r = *(const float4*)(B + (size_t)(k0 + br) * N + n0g + bc);
        }

#pragma unroll
        for (int kk = 0; kk < 16; kk += 8) {
            uint32_t af[2][4];
            uint32_t bf[4][2];
#pragma unroll
            for (int mt = 0; mt < 2; mt++) {
                const int mrow = wm * 32 + mt * 16 + t4;
                af[mt][0] = As[buf][mrow][kk + tq];
                af[mt][1] = As[buf][mrow + 8][kk + tq];
                af[mt][2] = As[buf][mrow][kk + tq + 4];
                af[mt][3] = As[buf][mrow + 8][kk + tq + 4];
            }
#pragma unroll
            for (int nt = 0; nt < 4; nt++) {
                const int ncol = wn * 32 + nt * 8 + t4;
                bf[nt][0] = Bsm[buf][kk + tq][ncol];
                bf[nt][1] = Bsm[buf][kk + tq + 4][ncol];
            }
#pragma unroll
            for (int mt = 0; mt < 2; mt++)
#pragma unroll
                for (int nt = 0; nt < 4; nt++)
                    mma_tf32(acc[mt][nt], af[mt], bf[nt]);
        }

        if (s + 1 < S) {
            const int nb = buf ^ 1;
            uint4 ua = {f2tf32(a0r.x), f2tf32(a0r.y), f2tf32(a0r.z), f2tf32(a0r.w)};
            *(uint4*)(&As[nb][ar0][ac0]) = ua;
            uint4 ub = {f2tf32(a1r.x), f2tf32(a1r.y), f2tf32(a1r.z), f2tf32(a1r.w)};
            *(uint4*)(&As[nb][ar1][ac1]) = ub;
            uint4 uc = {f2tf32(b0r.x), f2tf32(b0r.y), f2tf32(b0r.z), f2tf32(b0r.w)};
            *(uint4*)(&Bsm[nb][br][bc]) = uc;
        }
        __syncthreads();
    }

    // epilogue: add bias, store
#pragma unroll
    for (int nt = 0; nt < 4; nt++) {
        const int col = n0g + wn * 32 + nt * 8 + tq * 2;
        const float2 bb = *(const float2*)(bias + col);
#pragma unroll
        for (int mt = 0; mt < 2; mt++) {
            const int row = m0g + wm * 32 + mt * 16 + t4;
            float2 o0 = {acc[mt][nt][0] + bb.x, acc[mt][nt][1] + bb.y};
            float2 o1 = {acc[mt][nt][2] + bb.x, acc[mt][nt][3] + bb.y};
            *(float2*)(C + (size_t)row * N + col) = o0;
            *(float2*)(C + (size_t)(row + 8) * N + col) = o1;
        }
    }
}

// ---------------- fused softmax + deformable sampling (warp per (b,q)) -----
// Lane l: head h = l>>2, point j = l&3, channels [h*32 + j*8, +8) (2 float4).
// Each lane owns samples s = r*4 + j for levels r=0..3: precompute clamped
// corner token indices + softmax/bounds-folded weights into smem, then all
// lanes sweep the 16 samples of their head with vectorized gathers.
struct SampRec { int tok[4]; float w[4]; };

__global__ __launch_bounds__(256) void deform_sample2(
    const float* __restrict__ ref,   // [bs*nq, 4, 2]
    const float* __restrict__ off,   // [bs*nq, 256]
    const float* __restrict__ awr,   // [bs*nq, 128]
    const float* __restrict__ v,     // [bs*V, 256]
    float* __restrict__ out)         // [bs*nq, 256]
{
    __shared__ SampRec sm[8][128];   // 8 warps x (8 heads x 16 samples)

    const int w    = threadIdx.x >> 5;
    const int lane = threadIdx.x & 31;
    const int bq   = blockIdx.x * 8 + w;
    if (bq >= MROWS) return;
    const int b = bq / NQ;

    const int h = lane >> 2;
    const int j = lane & 3;

    // ---- phase 1: softmax + coordinates for this lane's 4 samples ----
    float lg[4];
#pragma unroll
    for (int r = 0; r < 4; r++)
        lg[r] = awr[(size_t)bq * 128 + h * 16 + r * 4 + j];

    float mx = fmaxf(fmaxf(lg[0], lg[1]), fmaxf(lg[2], lg[3]));
    mx = fmaxf(mx, __shfl_xor_sync(0xffffffffu, mx, 1));
    mx = fmaxf(mx, __shfl_xor_sync(0xffffffffu, mx, 2));
    float e[4], sum = 0.f;
#pragma unroll
    for (int r = 0; r < 4; r++) { e[r] = __expf(lg[r] - mx); sum += e[r]; }
    sum += __shfl_xor_sync(0xffffffffu, sum, 1);
    sum += __shfl_xor_sync(0xffffffffu, sum, 2);
    const float inv = 1.f / sum;

    const float2* offp = (const float2*)(off + (size_t)bq * 256);
    const float2* refp = (const float2*)(ref + (size_t)bq * 8);

#pragma unroll
    for (int r = 0; r < 4; r++) {
        const int s = r * 4 + j;
        const int W = c_dim[r];
        const int st = c_start[r];
        const float2 o2 = offp[h * 16 + s];
        const float2 r2 = refp[r];
        const float x = fmaf(r2.x, (float)W, o2.x) - 0.5f;
        const float y = fmaf(r2.y, (float)W, o2.y) - 0.5f;

        const float xf = floorf(x), yf = floorf(y);
        const int x0 = (int)xf, y0 = (int)yf;
        const float fx = x - xf, fy = y - yf;

        const float mx0 = ((unsigned)x0 < (unsigned)W) ? 1.f : 0.f;
        const float mx1 = ((unsigned)(x0 + 1) < (unsigned)W) ? 1.f : 0.f;
        const float my0 = ((unsigned)y0 < (unsigned)W) ? 1.f : 0.f;
        const float my1 = ((unsigned)(y0 + 1) < (unsigned)W) ? 1.f : 0.f;

        const float ww = e[r] * inv;
        const float wx0 = (1.f - fx) * mx0, wx1 = fx * mx1;
        const float wy0 = (1.f - fy) * my0, wy1 = fy * my1;

        const int xc0 = min(max(x0, 0), W - 1);
        const int xc1 = min(max(x0 + 1, 0), W - 1);
        const int yc0 = min(max(y0, 0), W - 1);
        const int yc1 = min(max(y0 + 1, 0), W - 1);

        SampRec rec;
        rec.tok[0] = st + yc0 * W + xc0;
        rec.tok[1] = st + yc0 * W + xc1;
        rec.tok[2] = st + yc1 * W + xc0;
        rec.tok[3] = st + yc1 * W + xc1;
        rec.w[0] = ww * wy0 * wx0;
        rec.w[1] = ww * wy0 * wx1;
        rec.w[2] = ww * wy1 * wx0;
        rec.w[3] = ww * wy1 * wx1;
        sm[w][h * 16 + s] = rec;
    }
    __syncwarp();

    // ---- phase 2: gather-accumulate 16 samples, 8 channels per lane ----
    const float* vb = v + (size_t)b * NQ * EMBED + h * HD + j * 8;
    float4 acc0 = {0.f, 0.f, 0.f, 0.f};
    float4 acc1 = {0.f, 0.f, 0.f, 0.f};

#pragma unroll
    for (int t = 0; t < 16; t++) {
        const SampRec rec = sm[w][h * 16 + t];
#pragma unroll
        for (int c = 0; c < 4; c++) {
            const float wt = rec.w[c];
            const float4* p = (const float4*)(vb + (size_t)rec.tok[c] * EMBED);
            const float4 p0 = p[0];
            const float4 p1 = p[1];
            acc0.x = fmaf(wt, p0.x, acc0.x);
            acc0.y = fmaf(wt, p0.y, acc0.y);
            acc0.z = fmaf(wt, p0.z, acc0.z);
            acc0.w = fmaf(wt, p0.w, acc0.w);
            acc1.x = fmaf(wt, p1.x, acc1.x);
            acc1.y = fmaf(wt, p1.y, acc1.y);
            acc1.z = fmaf(wt, p1.z, acc1.z);
            acc1.w = fmaf(wt, p1.w, acc1.w);
        }
    }

    float* op = out + (size_t)bq * EMBED + h * HD + j * 8;
    *(float4*)(op) = acc0;
    *(float4*)(op + 4) = acc1;
}

// ---------------- launch ----------------
extern "C" void kernel_launch(void* const* d_in, const int* in_sizes, int n_in,
                              void* d_out, int out_size)
{
    const float* query  = (const float*)d_in[0];
    const float* refpts = (const float*)d_in[1];
    const float* value  = (const float*)d_in[2];
    const float* W_off  = (const float*)d_in[3];
    const float* b_off  = (const float*)d_in[4];
    const float* W_attn = (const float*)d_in[5];
    const float* b_attn = (const float*)d_in[6];
    const float* W_v    = (const float*)d_in[7];
    const float* b_v    = (const float*)d_in[8];
    const float* W_out  = (const float*)d_in[9];
    const float* b_out  = (const float*)d_in[10];
    float* out = (float*)d_out;

    float *v_s, *off_s, *aw_s, *samp_s;
    cudaGetSymbolAddress((void**)&v_s,    g_v);
    cudaGetSymbolAddress((void**)&off_s,  g_off);
    cudaGetSymbolAddress((void**)&aw_s,   g_aw);
    cudaGetSymbolAddress((void**)&samp_s, g_samp);

    const dim3 blk(256);
    const dim3 g256(256 / 64, MROWS / 128);
    const dim3 g128(128 / 64, MROWS / 128);

    tgemm_tf32<<<g256, blk>>>(query, W_off, b_off, off_s, MROWS, 256, 256);
    tgemm_tf32<<<g128, blk>>>(query, W_attn, b_attn, aw_s, MROWS, 128, 256);
    tgemm_tf32<<<g256, blk>>>(value, W_v, b_v, v_s, MROWS, 256, 256);

    deform_sample2<<<MROWS / 8, blk>>>(refpts, off_s, aw_s, v_s, samp_s);

    tgemm_tf32<<<g256, blk>>>(samp_s, W_out, b_out, out, MROWS, 256, 256);
}

// round 3
// speedup vs baseline: 2.4289x; 1.2934x over previous
#include <cuda_runtime.h>
#include <cuda_bf16.h>
#include <cstdint>

// ---------------- problem constants ----------------
#define BS   2
#define NQ   21760
#define EMBED 256
#define NH   8
#define HD   32
#define MROWS (BS * NQ)   // 43520

__device__ __constant__ int c_dim[4]   = {128, 64, 32, 16};
__device__ __constant__ int c_start[4] = {0, 16384, 20480, 21504};

// ---------------- scratch ----------------
__device__ float g_v[MROWS * EMBED];
__device__ float g_off[MROWS * EMBED];
__device__ float g_aw[MROWS * 128];
__device__ float g_samp[MROWS * EMBED];

// ---------------- TF32 tensor-core GEMM ----------------
// C[M,N] = A[M,K] @ B[K,N] + bias[N].  BM=128, BN=128, BK=16, 256 thr (8 warps).
// Warp grid 2x4 (M x N), warp tile 64x32 via m16n8k8 (4 m-tiles x 4 n-tiles).
__device__ __forceinline__ uint32_t f2tf32(float x) {
    uint32_t r;
    asm("cvt.rna.tf32.f32 %0, %1;" : "=r"(r) : "f"(x));
    return r;
}

__device__ __forceinline__ void mma_tf32(float* d, const uint32_t* a,
                                         const uint32_t* b) {
    asm volatile(
        "mma.sync.aligned.m16n8k8.row.col.f32.tf32.tf32.f32 "
        "{%0,%1,%2,%3}, {%4,%5,%6,%7}, {%8,%9}, {%0,%1,%2,%3};"
        : "+f"(d[0]), "+f"(d[1]), "+f"(d[2]), "+f"(d[3])
        : "r"(a[0]), "r"(a[1]), "r"(a[2]), "r"(a[3]), "r"(b[0]), "r"(b[1]));
}

#define AS_STRIDE 20    // 16 + 4 pad: (20*t4 + tq) mod 32 -> conflict-free
#define BS_STRIDE 136   // 128 + 8 pad: 136%32==8 -> (8*tq + t4) conflict-free

__global__ __launch_bounds__(256) void tgemm_tf32(
    const float* __restrict__ A, const float* __restrict__ B,
    const float* __restrict__ bias, float* __restrict__ C,
    int M, int N, int K)
{
    __shared__ uint32_t As[2][128][AS_STRIDE];
    __shared__ uint32_t Bsm[2][16][BS_STRIDE];

    const int tid  = threadIdx.x;
    const int lane = tid & 31;
    const int wid  = tid >> 5;
    const int wm   = wid & 1;        // 0..1 -> 64-row group
    const int wn   = wid >> 1;       // 0..3 -> 32-col group
    const int t4   = lane >> 2;      // 0..7
    const int tq   = lane & 3;       // 0..3

    const int m0g = blockIdx.y * 128;
    const int n0g = blockIdx.x * 128;

    // A staging: 128x16 = 512 float4; thread loads 2
    const int ar0 = tid >> 2;
    const int ac0 = (tid & 3) * 4;
    const int ar1 = (tid + 256) >> 2;
    // B staging: 16x128 = 512 float4; thread loads 2
    const int br0 = tid >> 5;               // 0..7
    const int bc0 = (tid & 31) * 4;         // 0..124
    const int br1 = br0 + 8;                // 8..15

    float acc[4][4][4];
#pragma unroll
    for (int i = 0; i < 4; i++)
#pragma unroll
        for (int j = 0; j < 4; j++)
#pragma unroll
            for (int k = 0; k < 4; k++) acc[i][j][k] = 0.f;

    float4 a0r, a1r, b0r, b1r;
    const int S = K / 16;

    a0r = *(const float4*)(A + (size_t)(m0g + ar0) * K + ac0);
    a1r = *(const float4*)(A + (size_t)(m0g + ar1) * K + ac0);
    b0r = *(const float4*)(B + (size_t)br0 * N + n0g + bc0);
    b1r = *(const float4*)(B + (size_t)br1 * N + n0g + bc0);

    {
        uint4 u;
        u = make_uint4(f2tf32(a0r.x), f2tf32(a0r.y), f2tf32(a0r.z), f2tf32(a0r.w));
        *(uint4*)(&As[0][ar0][ac0]) = u;
        u = make_uint4(f2tf32(a1r.x), f2tf32(a1r.y), f2tf32(a1r.z), f2tf32(a1r.w));
        *(uint4*)(&As[0][ar1][ac0]) = u;
        u = make_uint4(f2tf32(b0r.x), f2tf32(b0r.y), f2tf32(b0r.z), f2tf32(b0r.w));
        *(uint4*)(&Bsm[0][br0][bc0]) = u;
        u = make_uint4(f2tf32(b1r.x), f2tf32(b1r.y), f2tf32(b1r.z), f2tf32(b1r.w));
        *(uint4*)(&Bsm[0][br1][bc0]) = u;
    }
    __syncthreads();

    for (int s = 0; s < S; s++) {
        const int buf = s & 1;
        if (s + 1 < S) {
            const int k0 = (s + 1) * 16;
            a0r = *(const float4*)(A + (size_t)(m0g + ar0) * K + k0 + ac0);
            a1r = *(const float4*)(A + (size_t)(m0g + ar1) * K + k0 + ac0);
            b0r = *(const float4*)(B + (size_t)(k0 + br0) * N + n0g + bc0);
            b1r = *(const float4*)(B + (size_t)(k0 + br1) * N + n0g + bc0);
        }

#pragma unroll
        for (int kk = 0; kk < 16; kk += 8) {
            uint32_t af[4][4];
            uint32_t bf[4][2];
#pragma unroll
            for (int mt = 0; mt < 4; mt++) {
                const int mrow = wm * 64 + mt * 16 + t4;
                af[mt][0] = As[buf][mrow][kk + tq];
                af[mt][1] = As[buf][mrow + 8][kk + tq];
                af[mt][2] = As[buf][mrow][kk + tq + 4];
                af[mt][3] = As[buf][mrow + 8][kk + tq + 4];
            }
#pragma unroll
            for (int nt = 0; nt < 4; nt++) {
                const int ncol = wn * 32 + nt * 8 + t4;
                bf[nt][0] = Bsm[buf][kk + tq][ncol];
                bf[nt][1] = Bsm[buf][kk + tq + 4][ncol];
            }
#pragma unroll
            for (int mt = 0; mt < 4; mt++)
#pragma unroll
                for (int nt = 0; nt < 4; nt++)
                    mma_tf32(acc[mt][nt], af[mt], bf[nt]);
        }

        if (s + 1 < S) {
            const int nb = buf ^ 1;
            uint4 u;
            u = make_uint4(f2tf32(a0r.x), f2tf32(a0r.y), f2tf32(a0r.z), f2tf32(a0r.w));
            *(uint4*)(&As[nb][ar0][ac0]) = u;
            u = make_uint4(f2tf32(a1r.x), f2tf32(a1r.y), f2tf32(a1r.z), f2tf32(a1r.w));
            *(uint4*)(&As[nb][ar1][ac0]) = u;
            u = make_uint4(f2tf32(b0r.x), f2tf32(b0r.y), f2tf32(b0r.z), f2tf32(b0r.w));
            *(uint4*)(&Bsm[nb][br0][bc0]) = u;
            u = make_uint4(f2tf32(b1r.x), f2tf32(b1r.y), f2tf32(b1r.z), f2tf32(b1r.w));
            *(uint4*)(&Bsm[nb][br1][bc0]) = u;
        }
        __syncthreads();
    }

#pragma unroll
    for (int nt = 0; nt < 4; nt++) {
        const int col = n0g + wn * 32 + nt * 8 + tq * 2;
        const float2 bb = *(const float2*)(bias + col);
#pragma unroll
        for (int mt = 0; mt < 4; mt++) {
            const int row = m0g + wm * 64 + mt * 16 + t4;
            float2 o0 = {acc[mt][nt][0] + bb.x, acc[mt][nt][1] + bb.y};
            float2 o1 = {acc[mt][nt][2] + bb.x, acc[mt][nt][3] + bb.y};
            *(float2*)(C + (size_t)row * N + col) = o0;
            *(float2*)(C + (size_t)(row + 8) * N + col) = o1;
        }
    }
}

// ---------------- fused softmax + deformable sampling (warp per (b,q)) -----
// Phase 1: lane -> (head h = lane>>2, point j = lane&3): softmax + corner
//          indices/weights for 4 samples (one per level) into smem.
// Phase 2: lane -> (hh = lane>>3, k = lane&7): 8 lanes cover one head's 32
//          channels -> every LDG.128 reads 4 FULL 128B lines per warp
//          (100% wavefront utilization). Two head-groups sweep all 8 heads.
struct __align__(16) SampRec { int tok[4]; float w[4]; };

__global__ __launch_bounds__(256) void deform_sample3(
    const float* __restrict__ ref,   // [bs*nq, 4, 2]
    const float* __restrict__ off,   // [bs*nq, 256]
    const float* __restrict__ awr,   // [bs*nq, 128]
    const float* __restrict__ v,     // [bs*V, 256]
    float* __restrict__ out)         // [bs*nq, 256]
{
    __shared__ SampRec sm[8][128];   // 8 warps x (8 heads x 16 samples)

    const int w    = threadIdx.x >> 5;
    const int lane = threadIdx.x & 31;
    const int bq   = blockIdx.x * 8 + w;
    const int b    = bq / NQ;

    {   // ---- phase 1 ----
        const int h = lane >> 2;
        const int j = lane & 3;

        float lg[4];
#pragma unroll
        for (int r = 0; r < 4; r++)
            lg[r] = awr[(size_t)bq * 128 + h * 16 + r * 4 + j];

        float mx = fmaxf(fmaxf(lg[0], lg[1]), fmaxf(lg[2], lg[3]));
        mx = fmaxf(mx, __shfl_xor_sync(0xffffffffu, mx, 1));
        mx = fmaxf(mx, __shfl_xor_sync(0xffffffffu, mx, 2));
        float e[4], sum = 0.f;
#pragma unroll
        for (int r = 0; r < 4; r++) { e[r] = __expf(lg[r] - mx); sum += e[r]; }
        sum += __shfl_xor_sync(0xffffffffu, sum, 1);
        sum += __shfl_xor_sync(0xffffffffu, sum, 2);
        const float inv = 1.f / sum;

        const float2* offp = (const float2*)(off + (size_t)bq * 256);
        const float2* refp = (const float2*)(ref + (size_t)bq * 8);

#pragma unroll
        for (int r = 0; r < 4; r++) {
            const int s = r * 4 + j;
            const int W = c_dim[r];
            const int st = c_start[r];
            const float2 o2 = offp[h * 16 + s];
            const float2 r2 = refp[r];
            const float x = fmaf(r2.x, (float)W, o2.x) - 0.5f;
            const float y = fmaf(r2.y, (float)W, o2.y) - 0.5f;

            const float xf = floorf(x), yf = floorf(y);
            const int x0 = (int)xf, y0 = (int)yf;
            const float fx = x - xf, fy = y - yf;

            const float mx0 = ((unsigned)x0 < (unsigned)W) ? 1.f : 0.f;
            const float mx1 = ((unsigned)(x0 + 1) < (unsigned)W) ? 1.f : 0.f;
            const float my0 = ((unsigned)y0 < (unsigned)W) ? 1.f : 0.f;
            const float my1 = ((unsigned)(y0 + 1) < (unsigned)W) ? 1.f : 0.f;

            const float ww = e[r] * inv;
            const float wx0 = (1.f - fx) * mx0, wx1 = fx * mx1;
            const float wy0 = (1.f - fy) * my0, wy1 = fy * my1;

            const int xc0 = min(max(x0, 0), W - 1);
            const int xc1 = min(max(x0 + 1, 0), W - 1);
            const int yc0 = min(max(y0, 0), W - 1);
            const int yc1 = min(max(y0 + 1, 0), W - 1);

            SampRec rec;
            rec.tok[0] = st + yc0 * W + xc0;
            rec.tok[1] = st + yc0 * W + xc1;
            rec.tok[2] = st + yc1 * W + xc0;
            rec.tok[3] = st + yc1 * W + xc1;
            rec.w[0] = ww * wy0 * wx0;
            rec.w[1] = ww * wy0 * wx1;
            rec.w[2] = ww * wy1 * wx0;
            rec.w[3] = ww * wy1 * wx1;
            sm[w][h * 16 + s] = rec;
        }
    }
    __syncwarp();

    // ---- phase 2: full-line gathers ----
    const int hh = lane >> 3;    // head within group (0..3)
    const int k  = lane & 7;     // float4 slot within 32 channels

    const float* vbase = v + (size_t)b * NQ * EMBED + k * 4;

#pragma unroll
    for (int g = 0; g < 2; g++) {
        const int h2 = g * 4 + hh;
        const float* vh = vbase + h2 * HD;
        float4 acc = {0.f, 0.f, 0.f, 0.f};

#pragma unroll 4
        for (int t = 0; t < 16; t++) {
            const SampRec rec = sm[w][h2 * 16 + t];
#pragma unroll
            for (int c = 0; c < 4; c++) {
                const float wt = rec.w[c];
                const float4 p = *(const float4*)(vh + (size_t)rec.tok[c] * EMBED);
                acc.x = fmaf(wt, p.x, acc.x);
                acc.y = fmaf(wt, p.y, acc.y);
                acc.z = fmaf(wt, p.z, acc.z);
                acc.w = fmaf(wt, p.w, acc.w);
            }
        }
        *(float4*)(out + (size_t)bq * EMBED + h2 * HD + k * 4) = acc;
    }
}

// ---------------- launch ----------------
extern "C" void kernel_launch(void* const* d_in, const int* in_sizes, int n_in,
                              void* d_out, int out_size)
{
    const float* query  = (const float*)d_in[0];
    const float* refpts = (const float*)d_in[1];
    const float* value  = (const float*)d_in[2];
    const float* W_off  = (const float*)d_in[3];
    const float* b_off  = (const float*)d_in[4];
    const float* W_attn = (const float*)d_in[5];
    const float* b_attn = (const float*)d_in[6];
    const float* W_v    = (const float*)d_in[7];
    const float* b_v    = (const float*)d_in[8];
    const float* W_out  = (const float*)d_in[9];
    const float* b_out  = (const float*)d_in[10];
    float* out = (float*)d_out;

    float *v_s, *off_s, *aw_s, *samp_s;
    cudaGetSymbolAddress((void**)&v_s,    g_v);
    cudaGetSymbolAddress((void**)&off_s,  g_off);
    cudaGetSymbolAddress((void**)&aw_s,   g_aw);
    cudaGetSymbolAddress((void**)&samp_s, g_samp);

    const dim3 blk(256);
    const dim3 g256(256 / 128, MROWS / 128);
    const dim3 g128(128 / 128, MROWS / 128);

    tgemm_tf32<<<g256, blk>>>(query, W_off, b_off, off_s, MROWS, 256, 256);
    tgemm_tf32<<<g128, blk>>>(query, W_attn, b_attn, aw_s, MROWS, 128, 256);
    tgemm_tf32<<<g256, blk>>>(value, W_v, b_v, v_s, MROWS, 256, 256);

    deform_sample3<<<MROWS / 8, blk>>>(refpts, off_s, aw_s, v_s, samp_s);

    tgemm_tf32<<<g256, blk>>>(samp_s, W_out, b_out, out, MROWS, 256, 256);
}

// round 6
// speedup vs baseline: 3.0386x; 1.2510x over previous
#include <cuda_runtime.h>
#include <cuda_fp16.h>
#include <cstdint>

// ---------------- problem constants ----------------
#define BS   2
#define NQ   21760
#define EMBED 256
#define NH   8
#define HD   32
#define MROWS (BS * NQ)   // 43520 = 340 * 128

__device__ __constant__ int c_dim[4]   = {128, 64, 32, 16};
__device__ __constant__ int c_start[4] = {0, 16384, 20480, 21504};

// ---------------- scratch ----------------
__device__ __align__(256) float  g_offaw[MROWS * 384];  // [.,0:256)=off, [.,256:384)=attn
__device__ __align__(256) __half g_vh[MROWS * EMBED];
__device__ __align__(256) float  g_samp[MROWS * EMBED];
__device__ __align__(256) float  g_wtcat[384 * EMBED];  // [W_off^T ; W_attn^T]
__device__ __align__(256) float  g_wtv[EMBED * EMBED];
__device__ __align__(256) float  g_wtout[EMBED * EMBED];
__device__ __align__(256) float  g_bcat[384];

// ---------------- helpers ----------------
__device__ __forceinline__ uint32_t smem_u32(const void* p) {
    uint32_t a;
    asm("{ .reg .u64 t; cvta.to.shared.u64 t, %1; cvt.u32.u64 %0, t; }"
        : "=r"(a) : "l"(p));
    return a;
}

#define SWZ(x) ((x) ^ (((x) >> 3) & 0x70))

#define LDSM4(r0, r1, r2, r3, addr)                                           \
    asm volatile("ldmatrix.sync.aligned.m8n8.x4.shared.b16 {%0,%1,%2,%3}, [%4];" \
                 : "=r"(r0), "=r"(r1), "=r"(r2), "=r"(r3) : "r"(addr))

__device__ __forceinline__ void mma_f16(float* d, const uint32_t* a,
                                        uint32_t b0, uint32_t b1) {
    asm volatile(
        "mma.sync.aligned.m16n8k16.row.col.f32.f16.f16.f32 "
        "{%0,%1,%2,%3}, {%4,%5,%6,%7}, {%8,%9}, {%0,%1,%2,%3};"
        : "+f"(d[0]), "+f"(d[1]), "+f"(d[2]), "+f"(d[3])
        : "r"(a[0]), "r"(a[1]), "r"(a[2]), "r"(a[3]), "r"(b0), "r"(b1));
}

// ---------------- weight transpose: out[C,R] = in[R,C] ----------------
__global__ void transpose_k(const float* __restrict__ in, float* __restrict__ out,
                            int R, int C)
{
    __shared__ float t[32][33];
    const int c0 = blockIdx.x * 32, r0 = blockIdx.y * 32;
    for (int i = threadIdx.y; i < 32; i += 8)
        t[i][threadIdx.x] = in[(size_t)(r0 + i) * C + c0 + threadIdx.x];
    __syncthreads();
    for (int i = threadIdx.y; i < 32; i += 8)
        out[(size_t)(c0 + i) * R + r0 + threadIdx.x] = t[threadIdx.x][i];
}

__global__ void concat_bias(const float* __restrict__ b0,
                            const float* __restrict__ b1,
                            float* __restrict__ out)
{
    const int i = threadIdx.x;
    out[i] = (i < 256) ? b0[i] : b1[i - 256];
}

// ---------------- fp16 tensor-core GEMM ----------------
// C[M, Nstr] tile (128 x 128) = A[M,256] @ Bt[N,256]^T + bias.
// K chunked by 32 floats (64B fp16 per row). Smem tile: 2 data-rows per
// 128B line, XOR swizzle on bits 4-6 keyed by bits 7-9. All swizzled
// addresses are computed by applying SWZ to the FULL logical offset of the
// 16B segment (the +32 k-step is folded in BEFORE the XOR; only the
// mt*1024 term, which can't touch bits 7-9, is added after).
// 8 warps (2x4), warp tile 64x32, m16n8k16 HMMA, fp32 accumulate.
template <bool HALF_OUT>
__global__ __launch_bounds__(256) void hgemm(
    const float* __restrict__ A, const float* __restrict__ Bt,
    const float* __restrict__ bias, void* __restrict__ C, int Nstr)
{
    __shared__ __align__(1024) uint8_t smA[2][8192];
    __shared__ __align__(1024) uint8_t smB[2][8192];

    const int tid  = threadIdx.x;
    const int lane = tid & 31;
    const int wid  = tid >> 5;
    const int wm   = wid & 1;        // 64-row group
    const int wn   = wid >> 1;       // 32-col group
    const int t4   = lane >> 2;
    const int tq   = lane & 3;

    const int m0 = blockIdx.y * 128;
    const int n0 = blockIdx.x * 128;

    // staging map: 128 rows x 4 x 16B segs; thread -> (row=tid>>2, seg=tid&3) x2
    const int r0s = tid >> 2;
    const int ps  = tid & 3;
    const int r1s = r0s + 64;
    const uint32_t stA = smem_u32(smA);
    const uint32_t stB = smem_u32(smB);
    const uint32_t so0 = SWZ((uint32_t)((r0s >> 1) * 128 + (r0s & 1) * 64 + ps * 16));
    const uint32_t so1 = SWZ((uint32_t)((r1s >> 1) * 128 + (r1s & 1) * 64 + ps * 16));

    // ldmatrix lane addressing: midx = which 8x8 matrix this lane addresses
    const int midx = lane >> 3;
    const int kseg = midx >> 1;                      // 0/1 -> k halves 0-7 / 8-15
    const int arow = wm * 64 + ((midx & 1) << 3) + (lane & 7);
    const uint32_t albase = (uint32_t)((arow >> 1) * 128 + (arow & 1) * 64 + kseg * 16);
    const uint32_t aoffk[2] = {SWZ(albase), SWZ(albase + 32)};
    const int brow = wn * 32 + ((midx & 1) << 3) + (lane & 7);
    const uint32_t blbase = (uint32_t)((brow >> 1) * 128 + (brow & 1) * 64 + kseg * 16);
    const uint32_t boffk[2] = {SWZ(blbase), SWZ(blbase + 32)};

    float acc[4][4][4];
#pragma unroll
    for (int i = 0; i < 4; i++)
#pragma unroll
        for (int j = 0; j < 4; j++)
#pragma unroll
            for (int k = 0; k < 4; k++) acc[i][j][k] = 0.f;

    float4 fa0, fa1, fa2, fa3, fb0, fb1, fb2, fb3;

    // prologue: LDG chunk 0  (each thread: 2 rows x 8 floats for A and B)
    {
        const float* pa0 = A + (size_t)(m0 + r0s) * 256 + ps * 8;
        const float* pa1 = A + (size_t)(m0 + r1s) * 256 + ps * 8;
        const float* pb0 = Bt + (size_t)(n0 + r0s) * 256 + ps * 8;
        const float* pb1 = Bt + (size_t)(n0 + r1s) * 256 + ps * 8;
        fa0 = *(const float4*)pa0; fa1 = *(const float4*)(pa0 + 4);
        fa2 = *(const float4*)pa1; fa3 = *(const float4*)(pa1 + 4);
        fb0 = *(const float4*)pb0; fb1 = *(const float4*)(pb0 + 4);
        fb2 = *(const float4*)pb1; fb3 = *(const float4*)(pb1 + 4);
    }

#pragma unroll 1
    for (int c = 0; c < 8; c++) {
        const int buf = c & 1;
        const uint32_t bufA = stA + buf * 8192;
        const uint32_t bufB = stB + buf * 8192;

        // convert + STS
        {
            __half2 h0 = __floats2half2_rn(fa0.x, fa0.y);
            __half2 h1 = __floats2half2_rn(fa0.z, fa0.w);
            __half2 h2 = __floats2half2_rn(fa1.x, fa1.y);
            __half2 h3 = __floats2half2_rn(fa1.z, fa1.w);
            asm volatile("st.shared.v4.b32 [%0], {%1,%2,%3,%4};" ::
                "r"(bufA + so0), "r"(*(uint32_t*)&h0), "r"(*(uint32_t*)&h1),
                "r"(*(uint32_t*)&h2), "r"(*(uint32_t*)&h3) : "memory");
            h0 = __floats2half2_rn(fa2.x, fa2.y);
            h1 = __floats2half2_rn(fa2.z, fa2.w);
            h2 = __floats2half2_rn(fa3.x, fa3.y);
            h3 = __floats2half2_rn(fa3.z, fa3.w);
            asm volatile("st.shared.v4.b32 [%0], {%1,%2,%3,%4};" ::
                "r"(bufA + so1), "r"(*(uint32_t*)&h0), "r"(*(uint32_t*)&h1),
                "r"(*(uint32_t*)&h2), "r"(*(uint32_t*)&h3) : "memory");
            h0 = __floats2half2_rn(fb0.x, fb0.y);
            h1 = __floats2half2_rn(fb0.z, fb0.w);
            h2 = __floats2half2_rn(fb1.x, fb1.y);
            h3 = __floats2half2_rn(fb1.z, fb1.w);
            asm volatile("st.shared.v4.b32 [%0], {%1,%2,%3,%4};" ::
                "r"(bufB + so0), "r"(*(uint32_t*)&h0), "r"(*(uint32_t*)&h1),
                "r"(*(uint32_t*)&h2), "r"(*(uint32_t*)&h3) : "memory");
            h0 = __floats2half2_rn(fb2.x, fb2.y);
            h1 = __floats2half2_rn(fb2.z, fb2.w);
            h2 = __floats2half2_rn(fb3.x, fb3.y);
            h3 = __floats2half2_rn(fb3.z, fb3.w);
            asm volatile("st.shared.v4.b32 [%0], {%1,%2,%3,%4};" ::
                "r"(bufB + so1), "r"(*(uint32_t*)&h0), "r"(*(uint32_t*)&h1),
                "r"(*(uint32_t*)&h2), "r"(*(uint32_t*)&h3) : "memory");
        }
        __syncthreads();

        // prefetch next chunk
        if (c < 7) {
            const int k0 = (c + 1) * 32;
            const float* pa0 = A + (size_t)(m0 + r0s) * 256 + k0 + ps * 8;
            const float* pa1 = A + (size_t)(m0 + r1s) * 256 + k0 + ps * 8;
            const float* pb0 = Bt + (size_t)(n0 + r0s) * 256 + k0 + ps * 8;
            const float* pb1 = Bt + (size_t)(n0 + r1s) * 256 + k0 + ps * 8;
            fa0 = *(const float4*)pa0; fa1 = *(const float4*)(pa0 + 4);
            fa2 = *(const float4*)pa1; fa3 = *(const float4*)(pa1 + 4);
            fb0 = *(const float4*)pb0; fb1 = *(const float4*)(pb0 + 4);
            fb2 = *(const float4*)pb1; fb3 = *(const float4*)(pb1 + 4);
        }

        // compute: 2 k-steps of m16n8k16
#pragma unroll
        for (int ks = 0; ks < 2; ks++) {
            uint32_t a[4][4], b[2][4];
#pragma unroll
            for (int mt = 0; mt < 4; mt++)
                LDSM4(a[mt][0], a[mt][1], a[mt][2], a[mt][3],
                      bufA + aoffk[ks] + mt * 1024);
#pragma unroll
            for (int np = 0; np < 2; np++)
                LDSM4(b[np][0], b[np][1], b[np][2], b[np][3],
                      bufB + boffk[ks] + np * 1024);
#pragma unroll
            for (int mt = 0; mt < 4; mt++)
#pragma unroll
                for (int nt = 0; nt < 4; nt++)
                    mma_f16(acc[mt][nt], a[mt], b[nt >> 1][nt & 1],
                            b[nt >> 1][(nt & 1) + 2]);
        }
        __syncthreads();
    }

    // epilogue
#pragma unroll
    for (int nt = 0; nt < 4; nt++) {
        const int col = n0 + wn * 32 + nt * 8 + tq * 2;
        const float2 bb = *(const float2*)(bias + col);
#pragma unroll
        for (int mt = 0; mt < 4; mt++) {
            const int row = m0 + wm * 64 + mt * 16 + t4;
            if (HALF_OUT) {
                __half2 h0 = __floats2half2_rn(acc[mt][nt][0] + bb.x,
                                               acc[mt][nt][1] + bb.y);
                __half2 h1 = __floats2half2_rn(acc[mt][nt][2] + bb.x,
                                               acc[mt][nt][3] + bb.y);
                *(uint32_t*)((__half*)C + (size_t)row * Nstr + col) = *(uint32_t*)&h0;
                *(uint32_t*)((__half*)C + (size_t)(row + 8) * Nstr + col) = *(uint32_t*)&h1;
            } else {
                float2 o0 = {acc[mt][nt][0] + bb.x, acc[mt][nt][1] + bb.y};
                float2 o1 = {acc[mt][nt][2] + bb.x, acc[mt][nt][3] + bb.y};
                *(float2*)((float*)C + (size_t)row * Nstr + col) = o0;
                *(float2*)((float*)C + (size_t)(row + 8) * Nstr + col) = o1;
            }
        }
    }
}

// ---------------- fused softmax + deformable sampling (fp16 value) ----------
struct __align__(16) SampRec { int tok[4]; float w[4]; };

__global__ __launch_bounds__(256) void deform_sample4(
    const float* __restrict__ ref, const float* __restrict__ offaw,
    const __half* __restrict__ vh, float* __restrict__ out)
{
    __shared__ SampRec sm[8][128];

    const int w    = threadIdx.x >> 5;
    const int lane = threadIdx.x & 31;
    const int bq   = blockIdx.x * 8 + w;
    const int b    = bq / NQ;
    const int h    = lane >> 2;
    const int j    = lane & 3;

    {   // ---- phase 1: softmax + corner precompute ----
        const float* aw = offaw + (size_t)bq * 384 + 256;
        float lg[4];
#pragma unroll
        for (int r = 0; r < 4; r++)
            lg[r] = aw[h * 16 + r * 4 + j];
        float mx = fmaxf(fmaxf(lg[0], lg[1]), fmaxf(lg[2], lg[3]));
        mx = fmaxf(mx, __shfl_xor_sync(0xffffffffu, mx, 1));
        mx = fmaxf(mx, __shfl_xor_sync(0xffffffffu, mx, 2));
        float e[4], sum = 0.f;
#pragma unroll
        for (int r = 0; r < 4; r++) { e[r] = __expf(lg[r] - mx); sum += e[r]; }
        sum += __shfl_xor_sync(0xffffffffu, sum, 1);
        sum += __shfl_xor_sync(0xffffffffu, sum, 2);
        const float inv = 1.f / sum;

        const float2* offp = (const float2*)(offaw + (size_t)bq * 384);
        const float2* refp = (const float2*)(ref + (size_t)bq * 8);
#pragma unroll
        for (int r = 0; r < 4; r++) {
            const int s = r * 4 + j;
            const int W = c_dim[r];
            const int st = c_start[r];
            const float2 o2 = offp[h * 16 + s];
            const float2 r2 = refp[r];
            const float x = fmaf(r2.x, (float)W, o2.x) - 0.5f;
            const float y = fmaf(r2.y, (float)W, o2.y) - 0.5f;
            const float xf = floorf(x), yf = floorf(y);
            const int x0 = (int)xf, y0 = (int)yf;
            const float fx = x - xf, fy = y - yf;
            const float mx0 = ((unsigned)x0 < (unsigned)W) ? 1.f : 0.f;
            const float mx1 = ((unsigned)(x0 + 1) < (unsigned)W) ? 1.f : 0.f;
            const float my0 = ((unsigned)y0 < (unsigned)W) ? 1.f : 0.f;
            const float my1 = ((unsigned)(y0 + 1) < (unsigned)W) ? 1.f : 0.f;
            const float ww = e[r] * inv;
            const float wx0 = (1.f - fx) * mx0, wx1 = fx * mx1;
            const float wy0 = (1.f - fy) * my0, wy1 = fy * my1;
            const int xc0 = min(max(x0, 0), W - 1);
            const int xc1 = min(max(x0 + 1, 0), W - 1);
            const int yc0 = min(max(y0, 0), W - 1);
            const int yc1 = min(max(y0 + 1, 0), W - 1);
            SampRec rec;
            rec.tok[0] = st + yc0 * W + xc0;
            rec.tok[1] = st + yc0 * W + xc1;
            rec.tok[2] = st + yc1 * W + xc0;
            rec.tok[3] = st + yc1 * W + xc1;
            rec.w[0] = ww * wy0 * wx0;
            rec.w[1] = ww * wy0 * wx1;
            rec.w[2] = ww * wy1 * wx0;
            rec.w[3] = ww * wy1 * wx1;
            sm[w][h * 16 + s] = rec;
        }
    }
    __syncwarp();

    // ---- phase 2: lane owns 8 channels; warp gather = full 512B token row --
    const __half* vb = vh + (size_t)b * NQ * EMBED + lane * 8;
    float4 acc0 = {0.f, 0.f, 0.f, 0.f};
    float4 acc1 = {0.f, 0.f, 0.f, 0.f};

#pragma unroll 4
    for (int t = 0; t < 16; t++) {
        const SampRec rec = sm[w][h * 16 + t];
#pragma unroll
        for (int c = 0; c < 4; c++) {
            const float wt = rec.w[c];
            const uint4 raw = *(const uint4*)(vb + (size_t)rec.tok[c] * EMBED);
            const float2 f0 = __half22float2(*(const __half2*)&raw.x);
            const float2 f1 = __half22float2(*(const __half2*)&raw.y);
            const float2 f2 = __half22float2(*(const __half2*)&raw.z);
            const float2 f3 = __half22float2(*(const __half2*)&raw.w);
            acc0.x = fmaf(wt, f0.x, acc0.x);
            acc0.y = fmaf(wt, f0.y, acc0.y);
            acc0.z = fmaf(wt, f1.x, acc0.z);
            acc0.w = fmaf(wt, f1.y, acc0.w);
            acc1.x = fmaf(wt, f2.x, acc1.x);
            acc1.y = fmaf(wt, f2.y, acc1.y);
            acc1.z = fmaf(wt, f3.x, acc1.z);
            acc1.w = fmaf(wt, f3.y, acc1.w);
        }
    }
    float* op = out + (size_t)bq * EMBED + lane * 8;
    *(float4*)op = acc0;
    *(float4*)(op + 4) = acc1;
}

// ---------------- launch ----------------
extern "C" void kernel_launch(void* const* d_in, const int* in_sizes, int n_in,
                              void* d_out, int out_size)
{
    const float* query  = (const float*)d_in[0];
    const float* refpts = (const float*)d_in[1];
    const float* value  = (const float*)d_in[2];
    const float* W_off  = (const float*)d_in[3];
    const float* b_off  = (const float*)d_in[4];
    const float* W_attn = (const float*)d_in[5];
    const float* b_attn = (const float*)d_in[6];
    const float* W_v    = (const float*)d_in[7];
    const float* b_v    = (const float*)d_in[8];
    const float* W_out  = (const float*)d_in[9];
    const float* b_out  = (const float*)d_in[10];
    float* out = (float*)d_out;

    float *offaw_s, *samp_s, *wtcat, *wtv, *wtout, *bcat;
    __half* vh_s;
    cudaGetSymbolAddress((void**)&offaw_s, g_offaw);
    cudaGetSymbolAddress((void**)&vh_s,    g_vh);
    cudaGetSymbolAddress((void**)&samp_s,  g_samp);
    cudaGetSymbolAddress((void**)&wtcat,   g_wtcat);
    cudaGetSymbolAddress((void**)&wtv,     g_wtv);
    cudaGetSymbolAddress((void**)&wtout,   g_wtout);
    cudaGetSymbolAddress((void**)&bcat,    g_bcat);

    // weight prep (tiny)
    transpose_k<<<dim3(8, 8), dim3(32, 8)>>>(W_off,  wtcat,             256, 256);
    transpose_k<<<dim3(4, 8), dim3(32, 8)>>>(W_attn, wtcat + 256 * 256, 256, 128);
    transpose_k<<<dim3(8, 8), dim3(32, 8)>>>(W_v,    wtv,               256, 256);
    transpose_k<<<dim3(8, 8), dim3(32, 8)>>>(W_out,  wtout,             256, 256);
    concat_bias<<<1, 384>>>(b_off, b_attn, bcat);

    const int GM = MROWS / 128;   // 340
    // fused offsets+attn GEMM: [M,384]
    hgemm<false><<<dim3(3, GM), 256>>>(query, wtcat, bcat, offaw_s, 384);
    // value projection -> fp16
    hgemm<true ><<<dim3(2, GM), 256>>>(value, wtv, b_v, vh_s, 256);

    deform_sample4<<<MROWS / 8, 256>>>(refpts, offaw_s, vh_s, samp_s);

    hgemm<false><<<dim3(2, GM), 256>>>(samp_s, wtout, b_out, out, 256);
}

// round 7
// speedup vs baseline: 3.3536x; 1.1037x over previous
#include <cuda_runtime.h>
#include <cuda_fp16.h>
#include <cstdint>

// ---------------- problem constants ----------------
#define BS   2
#define NQ   21760
#define EMBED 256
#define NH   8
#define HD   32
#define MROWS (BS * NQ)   // 43520 = 340 * 128

__device__ __constant__ int c_dim[4]   = {128, 64, 32, 16};
__device__ __constant__ int c_start[4] = {0, 16384, 20480, 21504};

// ---------------- scratch ----------------
__device__ __align__(256) float  g_offaw[MROWS * 384];   // off[0:256) | attn[256:384)
__device__ __align__(256) __half g_vhm[MROWS * EMBED];   // head-major: [b][h][tok][32]
__device__ __align__(256) __half g_samph[MROWS * EMBED]; // fp16 sampled output
__device__ __align__(256) __half g_wtcat[384 * EMBED];   // fp16 [Woff^T ; Wattn^T]
__device__ __align__(256) __half g_wtv[EMBED * EMBED];   // fp16 Wv^T
__device__ __align__(256) __half g_wtout[EMBED * EMBED]; // fp16 Wout^T
__device__ __align__(256) float  g_bcat[384];

// ---------------- helpers ----------------
__device__ __forceinline__ uint32_t smem_u32(const void* p) {
    uint32_t a;
    asm("{ .reg .u64 t; cvta.to.shared.u64 t, %1; cvt.u32.u64 %0, t; }"
        : "=r"(a) : "l"(p));
    return a;
}

#define SWZ(x) ((x) ^ (((x) >> 3) & 0x70))

#define LDSM4(r0, r1, r2, r3, addr)                                           \
    asm volatile("ldmatrix.sync.aligned.m8n8.x4.shared.b16 {%0,%1,%2,%3}, [%4];" \
                 : "=r"(r0), "=r"(r1), "=r"(r2), "=r"(r3) : "r"(addr))

#define STS16(addr, u)                                                        \
    asm volatile("st.shared.v4.b32 [%0], {%1,%2,%3,%4};"                      \
                 :: "r"(addr), "r"((u).x), "r"((u).y), "r"((u).z), "r"((u).w) : "memory")

__device__ __forceinline__ void mma_f16(float* d, const uint32_t* a,
                                        uint32_t b0, uint32_t b1) {
    asm volatile(
        "mma.sync.aligned.m16n8k16.row.col.f32.f16.f16.f32 "
        "{%0,%1,%2,%3}, {%4,%5,%6,%7}, {%8,%9}, {%0,%1,%2,%3};"
        : "+f"(d[0]), "+f"(d[1]), "+f"(d[2]), "+f"(d[3])
        : "r"(a[0]), "r"(a[1]), "r"(a[2]), "r"(a[3]), "r"(b0), "r"(b1));
}

// ---------------- weight prep: transpose + fp32->fp16, all weights, 1 launch
__global__ void prep_weights(const float* __restrict__ W_off,
                             const float* __restrict__ W_attn,
                             const float* __restrict__ W_v,
                             const float* __restrict__ W_out,
                             __half* __restrict__ wtcat,
                             __half* __restrict__ wtv,
                             __half* __restrict__ wtout)
{
    __shared__ float t[32][33];
    int bid = blockIdx.x;
    const float* in;
    __half* outb;
    int cx, ry;
    if (bid < 64)        { in = W_off;  outb = wtcat;          bid -= 0;   cx = bid & 7; ry = bid >> 3; }
    else if (bid < 96)   { in = W_attn; outb = wtcat + 65536;  bid -= 64;  cx = bid & 3; ry = bid >> 2; }
    else if (bid < 160)  { in = W_v;    outb = wtv;            bid -= 96;  cx = bid & 7; ry = bid >> 3; }
    else                 { in = W_out;  outb = wtout;          bid -= 160; cx = bid & 7; ry = bid >> 3; }
    const int C = (outb == wtcat + 65536) ? 128 : 256;   // source col count
    const int c0 = cx * 32, r0 = ry * 32;
    for (int i = threadIdx.y; i < 32; i += 8)
        t[i][threadIdx.x] = in[(size_t)(r0 + i) * C + c0 + threadIdx.x];
    __syncthreads();
    for (int i = threadIdx.y; i < 32; i += 8)
        outb[(size_t)(c0 + i) * 256 + r0 + threadIdx.x] = __float2half_rn(t[threadIdx.x][i]);
}

__global__ void concat_bias(const float* __restrict__ b0,
                            const float* __restrict__ b1,
                            float* __restrict__ out)
{
    const int i = threadIdx.x;
    out[i] = (i < 256) ? b0[i] : b1[i - 256];
}

// ---------------- fp16 tensor-core GEMM ----------------
// C tile (128x128) = A[M,256] @ Bt[N,256]^T + bias.  B always fp16; A fp32 or
// fp16 (A_HALF). OUTMODE: 0 = fp32 row-major (stride Nstr), 1 = fp16
// head-major v layout. 8 warps (2x4), warp tile 64x32, m16n8k16.
template <bool A_HALF, int OUTMODE>
__global__ __launch_bounds__(256) void hgemm(
    const void* __restrict__ Ain, const __half* __restrict__ Bt,
    const float* __restrict__ bias, void* __restrict__ C, int Nstr)
{
    __shared__ __align__(1024) uint8_t smA[2][8192];
    __shared__ __align__(1024) uint8_t smB[2][8192];

    const float*  Af = (const float*)Ain;
    const __half* Ah = (const __half*)Ain;

    const int tid  = threadIdx.x;
    const int lane = tid & 31;
    const int wid  = tid >> 5;
    const int wm   = wid & 1;
    const int wn   = wid >> 1;
    const int t4   = lane >> 2;
    const int tq   = lane & 3;

    const int m0 = blockIdx.y * 128;
    const int n0 = blockIdx.x * 128;

    const int r0s = tid >> 2;
    const int ps  = tid & 3;
    const int r1s = r0s + 64;
    const uint32_t stA = smem_u32(smA);
    const uint32_t stB = smem_u32(smB);
    const uint32_t so0 = SWZ((uint32_t)((r0s >> 1) * 128 + (r0s & 1) * 64 + ps * 16));
    const uint32_t so1 = SWZ((uint32_t)((r1s >> 1) * 128 + (r1s & 1) * 64 + ps * 16));

    const int midx = lane >> 3;
    const int kseg = midx >> 1;
    const int arow = wm * 64 + ((midx & 1) << 3) + (lane & 7);
    const uint32_t albase = (uint32_t)((arow >> 1) * 128 + (arow & 1) * 64 + kseg * 16);
    const uint32_t aoffk[2] = {SWZ(albase), SWZ(albase + 32)};
    const int brow = wn * 32 + ((midx & 1) << 3) + (lane & 7);
    const uint32_t blbase = (uint32_t)((brow >> 1) * 128 + (brow & 1) * 64 + kseg * 16);
    const uint32_t boffk[2] = {SWZ(blbase), SWZ(blbase + 32)};

    float acc[4][4][4];
#pragma unroll
    for (int i = 0; i < 4; i++)
#pragma unroll
        for (int j = 0; j < 4; j++)
#pragma unroll
            for (int k = 0; k < 4; k++) acc[i][j][k] = 0.f;

    float4 fa0, fa1, fa2, fa3;
    uint4 ha0, ha1, hb0, hb1;

    // prologue loads (chunk 0)
    if (A_HALF) {
        ha0 = *(const uint4*)(Ah + (size_t)(m0 + r0s) * 256 + ps * 8);
        ha1 = *(const uint4*)(Ah + (size_t)(m0 + r1s) * 256 + ps * 8);
    } else {
        const float* pa0 = Af + (size_t)(m0 + r0s) * 256 + ps * 8;
        const float* pa1 = Af + (size_t)(m0 + r1s) * 256 + ps * 8;
        fa0 = *(const float4*)pa0; fa1 = *(const float4*)(pa0 + 4);
        fa2 = *(const float4*)pa1; fa3 = *(const float4*)(pa1 + 4);
    }
    hb0 = *(const uint4*)(Bt + (size_t)(n0 + r0s) * 256 + ps * 8);
    hb1 = *(const uint4*)(Bt + (size_t)(n0 + r1s) * 256 + ps * 8);

#pragma unroll 1
    for (int c = 0; c < 8; c++) {
        const int buf = c & 1;
        const uint32_t bufA = stA + buf * 8192;
        const uint32_t bufB = stB + buf * 8192;

        if (A_HALF) {
            STS16(bufA + so0, ha0);
            STS16(bufA + so1, ha1);
        } else {
            __half2 h0 = __floats2half2_rn(fa0.x, fa0.y);
            __half2 h1 = __floats2half2_rn(fa0.z, fa0.w);
            __half2 h2 = __floats2half2_rn(fa1.x, fa1.y);
            __half2 h3 = __floats2half2_rn(fa1.z, fa1.w);
            uint4 u = make_uint4(*(uint32_t*)&h0, *(uint32_t*)&h1,
                                 *(uint32_t*)&h2, *(uint32_t*)&h3);
            STS16(bufA + so0, u);
            h0 = __floats2half2_rn(fa2.x, fa2.y);
            h1 = __floats2half2_rn(fa2.z, fa2.w);
            h2 = __floats2half2_rn(fa3.x, fa3.y);
            h3 = __floats2half2_rn(fa3.z, fa3.w);
            u = make_uint4(*(uint32_t*)&h0, *(uint32_t*)&h1,
                           *(uint32_t*)&h2, *(uint32_t*)&h3);
            STS16(bufA + so1, u);
        }
        STS16(bufB + so0, hb0);
        STS16(bufB + so1, hb1);
        __syncthreads();

        if (c < 7) {
            const int k0 = (c + 1) * 32;
            if (A_HALF) {
                ha0 = *(const uint4*)(Ah + (size_t)(m0 + r0s) * 256 + k0 + ps * 8);
                ha1 = *(const uint4*)(Ah + (size_t)(m0 + r1s) * 256 + k0 + ps * 8);
            } else {
                const float* pa0 = Af + (size_t)(m0 + r0s) * 256 + k0 + ps * 8;
                const float* pa1 = Af + (size_t)(m0 + r1s) * 256 + k0 + ps * 8;
                fa0 = *(const float4*)pa0; fa1 = *(const float4*)(pa0 + 4);
                fa2 = *(const float4*)pa1; fa3 = *(const float4*)(pa1 + 4);
            }
            hb0 = *(const uint4*)(Bt + (size_t)(n0 + r0s) * 256 + k0 + ps * 8);
            hb1 = *(const uint4*)(Bt + (size_t)(n0 + r1s) * 256 + k0 + ps * 8);
        }

#pragma unroll
        for (int ks = 0; ks < 2; ks++) {
            uint32_t a[4][4], b[2][4];
#pragma unroll
            for (int mt = 0; mt < 4; mt++)
                LDSM4(a[mt][0], a[mt][1], a[mt][2], a[mt][3],
                      bufA + aoffk[ks] + mt * 1024);
#pragma unroll
            for (int np = 0; np < 2; np++)
                LDSM4(b[np][0], b[np][1], b[np][2], b[np][3],
                      bufB + boffk[ks] + np * 1024);
#pragma unroll
            for (int mt = 0; mt < 4; mt++)
#pragma unroll
                for (int nt = 0; nt < 4; nt++)
                    mma_f16(acc[mt][nt], a[mt], b[nt >> 1][nt & 1],
                            b[nt >> 1][(nt & 1) + 2]);
        }
        __syncthreads();
    }

    // epilogue
#pragma unroll
    for (int nt = 0; nt < 4; nt++) {
        const int col = n0 + wn * 32 + nt * 8 + tq * 2;
        const float2 bb = *(const float2*)(bias + col);
#pragma unroll
        for (int mt = 0; mt < 4; mt++) {
            const int row = m0 + wm * 64 + mt * 16 + t4;
            if (OUTMODE == 0) {
                float2 o0 = {acc[mt][nt][0] + bb.x, acc[mt][nt][1] + bb.y};
                float2 o1 = {acc[mt][nt][2] + bb.x, acc[mt][nt][3] + bb.y};
                *(float2*)((float*)C + (size_t)row * Nstr + col) = o0;
                *(float2*)((float*)C + (size_t)(row + 8) * Nstr + col) = o1;
            } else {
                // head-major fp16: v[b][h][tok][32]
                const int h = col >> 5, ch = col & 31;
                __half2 h0 = __floats2half2_rn(acc[mt][nt][0] + bb.x,
                                               acc[mt][nt][1] + bb.y);
                __half2 h1 = __floats2half2_rn(acc[mt][nt][2] + bb.x,
                                               acc[mt][nt][3] + bb.y);
                const int b0i = row / NQ,       tok0 = row - b0i * NQ;
                const int b1i = (row + 8) / NQ, tok1 = (row + 8) - b1i * NQ;
                __half* V = (__half*)C;
                *(uint32_t*)(V + (((size_t)b0i * 8 + h) * NQ + tok0) * 32 + ch) =
                    *(uint32_t*)&h0;
                *(uint32_t*)(V + (((size_t)b1i * 8 + h) * NQ + tok1) * 32 + ch) =
                    *(uint32_t*)&h1;
            }
        }
    }
}

// ---------------- fused softmax + deformable sampling -----------------------
// Phase 1 (lane = head*4+point): softmax + 4 corner tokens/weights per level.
// Phase 2: head-major fp16 v; one LDG packs 4 (sample,y-row) items, each item
// = x-adjacent corner PAIR (contiguous 128B in head-major layout -> 1-2 lines
// instead of 2). Cross-lane shfl reduction folds corner/item partials.
struct __align__(16) SampRec { int tok[4]; float w[4]; };

__global__ __launch_bounds__(256) void deform_sample5(
    const float* __restrict__ ref, const float* __restrict__ offaw,
    const __half* __restrict__ vhm, __half* __restrict__ samph)
{
    __shared__ SampRec sm[8][128];

    const int w    = threadIdx.x >> 5;
    const int lane = threadIdx.x & 31;
    const int bq   = blockIdx.x * 8 + w;
    const int b    = bq / NQ;

    {   // ---- phase 1 ----
        const int h = lane >> 2;
        const int j = lane & 3;
        const float* aw = offaw + (size_t)bq * 384 + 256;
        float lg[4];
#pragma unroll
        for (int r = 0; r < 4; r++) lg[r] = aw[h * 16 + r * 4 + j];
        float mx = fmaxf(fmaxf(lg[0], lg[1]), fmaxf(lg[2], lg[3]));
        mx = fmaxf(mx, __shfl_xor_sync(0xffffffffu, mx, 1));
        mx = fmaxf(mx, __shfl_xor_sync(0xffffffffu, mx, 2));
        float e[4], sum = 0.f;
#pragma unroll
        for (int r = 0; r < 4; r++) { e[r] = __expf(lg[r] - mx); sum += e[r]; }
        sum += __shfl_xor_sync(0xffffffffu, sum, 1);
        sum += __shfl_xor_sync(0xffffffffu, sum, 2);
        const float inv = 1.f / sum;

        const float2* offp = (const float2*)(offaw + (size_t)bq * 384);
        const float2* refp = (const float2*)(ref + (size_t)bq * 8);
#pragma unroll
        for (int r = 0; r < 4; r++) {
            const int s = r * 4 + j;
            const int W = c_dim[r];
            const int st = c_start[r];
            const float2 o2 = offp[h * 16 + s];
            const float2 r2 = refp[r];
            const float x = fmaf(r2.x, (float)W, o2.x) - 0.5f;
            const float y = fmaf(r2.y, (float)W, o2.y) - 0.5f;
            const float xf = floorf(x), yf = floorf(y);
            const int x0 = (int)xf, y0 = (int)yf;
            const float fx = x - xf, fy = y - yf;
            const float mx0 = ((unsigned)x0 < (unsigned)W) ? 1.f : 0.f;
            const float mx1 = ((unsigned)(x0 + 1) < (unsigned)W) ? 1.f : 0.f;
            const float my0 = ((unsigned)y0 < (unsigned)W) ? 1.f : 0.f;
            const float my1 = ((unsigned)(y0 + 1) < (unsigned)W) ? 1.f : 0.f;
            const float ww = e[r] * inv;
            const float wx0 = (1.f - fx) * mx0, wx1 = fx * mx1;
            const float wy0 = (1.f - fy) * my0, wy1 = fy * my1;
            const int xc0 = min(max(x0, 0), W - 1);
            const int xc1 = min(max(x0 + 1, 0), W - 1);
            const int yc0 = min(max(y0, 0), W - 1);
            const int yc1 = min(max(y0 + 1, 0), W - 1);
            SampRec rec;
            rec.tok[0] = st + yc0 * W + xc0;
            rec.tok[1] = st + yc0 * W + xc1;
            rec.tok[2] = st + yc1 * W + xc0;
            rec.tok[3] = st + yc1 * W + xc1;
            rec.w[0] = ww * wy0 * wx0;
            rec.w[1] = ww * wy0 * wx1;
            rec.w[2] = ww * wy1 * wx0;
            rec.w[3] = ww * wy1 * wx1;
            sm[w][h * 16 + s] = rec;
        }
    }
    __syncwarp();

    // ---- phase 2 ----
    const int item_hi = lane >> 3;      // which of 4 items in this LDG
    const int sub     = lane & 7;
    const int c2      = sub >> 2;       // corner within x-pair
    const int chsl    = sub & 3;        // 8-channel slice

#pragma unroll 1
    for (int h = 0; h < 8; h++) {
        const __half* vbh = vhm + ((size_t)(b * 8 + h)) * (NQ * 32);
        float av[8];
#pragma unroll
        for (int k = 0; k < 8; k++) av[k] = 0.f;

#pragma unroll
        for (int ldg = 0; ldg < 8; ldg++) {
            const int it  = ldg * 4 + item_hi;   // 0..31
            const int t   = it >> 1;             // sample
            const int row = it & 1;              // y-row (top/bottom)
            const int i4  = row * 2 + c2;
            const int tok = sm[w][h * 16 + t].tok[i4];
            const float wt = sm[w][h * 16 + t].w[i4];
            const uint4 raw = *(const uint4*)(vbh + (size_t)tok * 32 + chsl * 8);
            const float2 f0 = __half22float2(*(const __half2*)&raw.x);
            const float2 f1 = __half22float2(*(const __half2*)&raw.y);
            const float2 f2 = __half22float2(*(const __half2*)&raw.z);
            const float2 f3 = __half22float2(*(const __half2*)&raw.w);
            av[0] = fmaf(wt, f0.x, av[0]);
            av[1] = fmaf(wt, f0.y, av[1]);
            av[2] = fmaf(wt, f1.x, av[2]);
            av[3] = fmaf(wt, f1.y, av[3]);
            av[4] = fmaf(wt, f2.x, av[4]);
            av[5] = fmaf(wt, f2.y, av[5]);
            av[6] = fmaf(wt, f3.x, av[6]);
            av[7] = fmaf(wt, f3.y, av[7]);
        }

        // reduce over lane bits 2,3,4 (corner + item slots)
#pragma unroll
        for (int o = 4; o <= 16; o <<= 1)
#pragma unroll
            for (int k = 0; k < 8; k++)
                av[k] += __shfl_xor_sync(0xffffffffu, av[k], o);

        if (lane < 4) {
            __half2 h0 = __floats2half2_rn(av[0], av[1]);
            __half2 h1 = __floats2half2_rn(av[2], av[3]);
            __half2 h2 = __floats2half2_rn(av[4], av[5]);
            __half2 h3 = __floats2half2_rn(av[6], av[7]);
            uint4 u = make_uint4(*(uint32_t*)&h0, *(uint32_t*)&h1,
                                 *(uint32_t*)&h2, *(uint32_t*)&h3);
            *(uint4*)(samph + (size_t)bq * 256 + h * 32 + lane * 8) = u;
        }
    }
}

// ---------------- launch ----------------
extern "C" void kernel_launch(void* const* d_in, const int* in_sizes, int n_in,
                              void* d_out, int out_size)
{
    const float* query  = (const float*)d_in[0];
    const float* refpts = (const float*)d_in[1];
    const float* value  = (const float*)d_in[2];
    const float* W_off  = (const float*)d_in[3];
    const float* b_off  = (const float*)d_in[4];
    const float* W_attn = (const float*)d_in[5];
    const float* b_attn = (const float*)d_in[6];
    const float* W_v    = (const float*)d_in[7];
    const float* b_v    = (const float*)d_in[8];
    const float* W_out  = (const float*)d_in[9];
    const float* b_out  = (const float*)d_in[10];
    float* out = (float*)d_out;

    float *offaw_s, *bcat;
    __half *vhm_s, *samph_s, *wtcat, *wtv, *wtout;
    cudaGetSymbolAddress((void**)&offaw_s, g_offaw);
    cudaGetSymbolAddress((void**)&vhm_s,   g_vhm);
    cudaGetSymbolAddress((void**)&samph_s, g_samph);
    cudaGetSymbolAddress((void**)&wtcat,   g_wtcat);
    cudaGetSymbolAddress((void**)&wtv,     g_wtv);
    cudaGetSymbolAddress((void**)&wtout,   g_wtout);
    cudaGetSymbolAddress((void**)&bcat,    g_bcat);

    prep_weights<<<224, dim3(32, 8)>>>(W_off, W_attn, W_v, W_out,
                                       wtcat, wtv, wtout);
    concat_bias<<<1, 384>>>(b_off, b_attn, bcat);

    const int GM = MROWS / 128;   // 340
    hgemm<false, 0><<<dim3(3, GM), 256>>>(query, wtcat, bcat, offaw_s, 384);
    hgemm<false, 1><<<dim3(2, GM), 256>>>(value, wtv, b_v, vhm_s, 256);

    deform_sample5<<<MROWS / 8, 256>>>(refpts, offaw_s, vhm_s, samph_s);

    hgemm<true, 0><<<dim3(2, GM), 256>>>(samph_s, wtout, b_out, out, 256);
}

// round 8
// speedup vs baseline: 3.4736x; 1.0358x over previous
#include <cuda_runtime.h>
#include <cuda_fp16.h>
#include <cstdint>

// ---------------- problem constants ----------------
#define BS   2
#define NQ   21760
#define EMBED 256
#define NH   8
#define HD   32
#define MROWS (BS * NQ)   // 43520 = 340 * 128

__device__ __constant__ int c_dim[4]   = {128, 64, 32, 16};
__device__ __constant__ int c_start[4] = {0, 16384, 20480, 21504};

// ---------------- scratch ----------------
__device__ __align__(256) __half g_qh[MROWS * EMBED];    // fp16 query
__device__ __align__(256) __half g_valh[MROWS * EMBED];  // fp16 value
__device__ __align__(256) float  g_offaw[MROWS * 384];   // off[0:256) | attn[256:384)
__device__ __align__(256) __half g_vhm[MROWS * EMBED];   // head-major: [b][h][tok][32]
__device__ __align__(256) __half g_samph[MROWS * EMBED]; // fp16 sampled output
__device__ __align__(256) __half g_wtcat[384 * EMBED];   // fp16 [Woff^T ; Wattn^T]
__device__ __align__(256) __half g_wtv[EMBED * EMBED];   // fp16 Wv^T
__device__ __align__(256) __half g_wtout[EMBED * EMBED]; // fp16 Wout^T
__device__ __align__(256) float  g_bcat[384];

// ---------------- helpers ----------------
__device__ __forceinline__ uint32_t smem_u32(const void* p) {
    uint32_t a;
    asm("{ .reg .u64 t; cvta.to.shared.u64 t, %1; cvt.u32.u64 %0, t; }"
        : "=r"(a) : "l"(p));
    return a;
}

#define SWZ(x) ((x) ^ (((x) >> 3) & 0x70))

#define LDSM4(r0, r1, r2, r3, addr)                                           \
    asm volatile("ldmatrix.sync.aligned.m8n8.x4.shared.b16 {%0,%1,%2,%3}, [%4];" \
                 : "=r"(r0), "=r"(r1), "=r"(r2), "=r"(r3) : "r"(addr))

#define CP16(dst, src)                                                        \
    asm volatile("cp.async.cg.shared.global [%0], [%1], 16;"                  \
                 :: "r"(dst), "l"(src) : "memory")
#define CP_COMMIT asm volatile("cp.async.commit_group;" ::: "memory")
#define CP_WAIT2  asm volatile("cp.async.wait_group 2;" ::: "memory")

__device__ __forceinline__ void mma_f16(float* d, const uint32_t* a,
                                        uint32_t b0, uint32_t b1) {
    asm volatile(
        "mma.sync.aligned.m16n8k16.row.col.f32.f16.f16.f32 "
        "{%0,%1,%2,%3}, {%4,%5,%6,%7}, {%8,%9}, {%0,%1,%2,%3};"
        : "+f"(d[0]), "+f"(d[1]), "+f"(d[2]), "+f"(d[3])
        : "r"(a[0]), "r"(a[1]), "r"(a[2]), "r"(a[3]), "r"(b0), "r"(b1));
}

// ---------------- prep kernels ----------------
__global__ void prep_weights(const float* __restrict__ W_off,
                             const float* __restrict__ W_attn,
                             const float* __restrict__ W_v,
                             const float* __restrict__ W_out,
                             __half* __restrict__ wtcat,
                             __half* __restrict__ wtv,
                             __half* __restrict__ wtout)
{
    __shared__ float t[32][33];
    int bid = blockIdx.x;
    const float* in;
    __half* outb;
    int cx, ry;
    if (bid < 64)        { in = W_off;  outb = wtcat;          bid -= 0;   cx = bid & 7; ry = bid >> 3; }
    else if (bid < 96)   { in = W_attn; outb = wtcat + 65536;  bid -= 64;  cx = bid & 3; ry = bid >> 2; }
    else if (bid < 160)  { in = W_v;    outb = wtv;            bid -= 96;  cx = bid & 7; ry = bid >> 3; }
    else                 { in = W_out;  outb = wtout;          bid -= 160; cx = bid & 7; ry = bid >> 3; }
    const int C = (outb == wtcat + 65536) ? 128 : 256;
    const int c0 = cx * 32, r0 = ry * 32;
    for (int i = threadIdx.y; i < 32; i += 8)
        t[i][threadIdx.x] = in[(size_t)(r0 + i) * C + c0 + threadIdx.x];
    __syncthreads();
    for (int i = threadIdx.y; i < 32; i += 8)
        outb[(size_t)(c0 + i) * 256 + r0 + threadIdx.x] = __float2half_rn(t[threadIdx.x][i]);
}

__global__ void concat_bias(const float* __restrict__ b0,
                            const float* __restrict__ b1,
                            float* __restrict__ out)
{
    const int i = threadIdx.x;
    out[i] = (i < 256) ? b0[i] : b1[i - 256];
}

// fp32 -> fp16 bulk convert (4 floats / thread)
__global__ void f2h(const float* __restrict__ in, __half* __restrict__ out)
{
    const size_t i = ((size_t)blockIdx.x * 256 + threadIdx.x) * 4;
    const float4 v = *(const float4*)(in + i);
    __half2 h0 = __floats2half2_rn(v.x, v.y);
    __half2 h1 = __floats2half2_rn(v.z, v.w);
    *(uint2*)(out + i) = make_uint2(*(uint32_t*)&h0, *(uint32_t*)&h1);
}

// ---------------- fp16 tensor-core GEMM (cp.async 4-stage) ----------------
// C tile (128x128) = A[M,256] @ Bt[N,256]^T + bias.  Both operands fp16.
// OUTMODE: 0 = fp32 row-major (stride Nstr), 1 = fp16 head-major v layout.
// 8 warps (2x4), warp tile 64x32, m16n8k16, fp32 accumulate, 2 CTAs/SM.
template <int OUTMODE>
__global__ __launch_bounds__(256, 2) void hgemm(
    const __half* __restrict__ A, const __half* __restrict__ Bt,
    const float* __restrict__ bias, void* __restrict__ C, int Nstr)
{
    extern __shared__ __align__(1024) uint8_t smem[];
    const uint32_t stA = smem_u32(smem);             // 4 x 8KB
    const uint32_t stB = stA + 32768;                // 4 x 8KB

    const int tid  = threadIdx.x;
    const int lane = tid & 31;
    const int wid  = tid >> 5;
    const int wm   = wid & 1;
    const int wn   = wid >> 1;
    const int t4   = lane >> 2;
    const int tq   = lane & 3;

    const int m0 = blockIdx.y * 128;
    const int n0 = blockIdx.x * 128;

    // staging map: 128 rows x 4 x 16B segs; thread -> (row, seg) x2
    const int r0s = tid >> 2;
    const int ps  = tid & 3;
    const int r1s = r0s + 64;
    const uint32_t so0 = SWZ((uint32_t)((r0s >> 1) * 128 + (r0s & 1) * 64 + ps * 16));
    const uint32_t so1 = SWZ((uint32_t)((r1s >> 1) * 128 + (r1s & 1) * 64 + ps * 16));

    const __half* pa0 = A + (size_t)(m0 + r0s) * 256 + ps * 8;
    const __half* pa1 = A + (size_t)(m0 + r1s) * 256 + ps * 8;
    const __half* pb0 = Bt + (size_t)(n0 + r0s) * 256 + ps * 8;
    const __half* pb1 = Bt + (size_t)(n0 + r1s) * 256 + ps * 8;

    // ldmatrix lane addressing
    const int midx = lane >> 3;
    const int kseg = midx >> 1;
    const int arow = wm * 64 + ((midx & 1) << 3) + (lane & 7);
    const uint32_t albase = (uint32_t)((arow >> 1) * 128 + (arow & 1) * 64 + kseg * 16);
    const uint32_t aoffk[2] = {SWZ(albase), SWZ(albase + 32)};
    const int brow = wn * 32 + ((midx & 1) << 3) + (lane & 7);
    const uint32_t blbase = (uint32_t)((brow >> 1) * 128 + (brow & 1) * 64 + kseg * 16);
    const uint32_t boffk[2] = {SWZ(blbase), SWZ(blbase + 32)};

    float acc[4][4][4];
#pragma unroll
    for (int i = 0; i < 4; i++)
#pragma unroll
        for (int j = 0; j < 4; j++)
#pragma unroll
            for (int k = 0; k < 4; k++) acc[i][j][k] = 0.f;

    // prologue: issue chunks 0..2
#pragma unroll
    for (int s = 0; s < 3; s++) {
        const uint32_t bA = stA + s * 8192, bB = stB + s * 8192;
        const int ko = s * 32;
        CP16(bA + so0, pa0 + ko);
        CP16(bA + so1, pa1 + ko);
        CP16(bB + so0, pb0 + ko);
        CP16(bB + so1, pb1 + ko);
        CP_COMMIT;
    }

#pragma unroll 1
    for (int c = 0; c < 8; c++) {
        CP_WAIT2;
        __syncthreads();

        if (c + 3 < 8) {
            const int s = c + 3;
            const uint32_t bA = stA + (s & 3) * 8192, bB = stB + (s & 3) * 8192;
            const int ko = s * 32;
            CP16(bA + so0, pa0 + ko);
            CP16(bA + so1, pa1 + ko);
            CP16(bB + so0, pb0 + ko);
            CP16(bB + so1, pb1 + ko);
        }
        CP_COMMIT;   // commit every iter so wait_group 2 is uniformly correct

        const uint32_t bufA = stA + (c & 3) * 8192;
        const uint32_t bufB = stB + (c & 3) * 8192;

#pragma unroll
        for (int ks = 0; ks < 2; ks++) {
            uint32_t a[4][4], b[2][4];
#pragma unroll
            for (int mt = 0; mt < 4; mt++)
                LDSM4(a[mt][0], a[mt][1], a[mt][2], a[mt][3],
                      bufA + aoffk[ks] + mt * 1024);
#pragma unroll
            for (int np = 0; np < 2; np++)
                LDSM4(b[np][0], b[np][1], b[np][2], b[np][3],
                      bufB + boffk[ks] + np * 1024);
#pragma unroll
            for (int mt = 0; mt < 4; mt++)
#pragma unroll
                for (int nt = 0; nt < 4; nt++)
                    mma_f16(acc[mt][nt], a[mt], b[nt >> 1][nt & 1],
                            b[nt >> 1][(nt & 1) + 2]);
        }
    }

    // epilogue
#pragma unroll
    for (int nt = 0; nt < 4; nt++) {
        const int col = n0 + wn * 32 + nt * 8 + tq * 2;
        const float2 bb = *(const float2*)(bias + col);
#pragma unroll
        for (int mt = 0; mt < 4; mt++) {
            const int row = m0 + wm * 64 + mt * 16 + t4;
            if (OUTMODE == 0) {
                float2 o0 = {acc[mt][nt][0] + bb.x, acc[mt][nt][1] + bb.y};
                float2 o1 = {acc[mt][nt][2] + bb.x, acc[mt][nt][3] + bb.y};
                *(float2*)((float*)C + (size_t)row * Nstr + col) = o0;
                *(float2*)((float*)C + (size_t)(row + 8) * Nstr + col) = o1;
            } else {
                const int h = col >> 5, ch = col & 31;
                __half2 h0 = __floats2half2_rn(acc[mt][nt][0] + bb.x,
                                               acc[mt][nt][1] + bb.y);
                __half2 h1 = __floats2half2_rn(acc[mt][nt][2] + bb.x,
                                               acc[mt][nt][3] + bb.y);
                const int b0i = row / NQ,       tok0 = row - b0i * NQ;
                const int b1i = (row + 8) / NQ, tok1 = (row + 8) - b1i * NQ;
                __half* V = (__half*)C;
                *(uint32_t*)(V + (((size_t)b0i * 8 + h) * NQ + tok0) * 32 + ch) =
                    *(uint32_t*)&h0;
                *(uint32_t*)(V + (((size_t)b1i * 8 + h) * NQ + tok1) * 32 + ch) =
                    *(uint32_t*)&h1;
            }
        }
    }
}

// ---------------- fused softmax + deformable sampling -----------------------
struct __align__(16) SampRec { int tok[4]; float w[4]; };

__global__ __launch_bounds__(256) void deform_sample5(
    const float* __restrict__ ref, const float* __restrict__ offaw,
    const __half* __restrict__ vhm, __half* __restrict__ samph)
{
    __shared__ SampRec sm[8][128];

    const int w    = threadIdx.x >> 5;
    const int lane = threadIdx.x & 31;
    const int bq   = blockIdx.x * 8 + w;
    const int b    = bq / NQ;

    {   // ---- phase 1 ----
        const int h = lane >> 2;
        const int j = lane & 3;
        const float* aw = offaw + (size_t)bq * 384 + 256;
        float lg[4];
#pragma unroll
        for (int r = 0; r < 4; r++) lg[r] = aw[h * 16 + r * 4 + j];
        float mx = fmaxf(fmaxf(lg[0], lg[1]), fmaxf(lg[2], lg[3]));
        mx = fmaxf(mx, __shfl_xor_sync(0xffffffffu, mx, 1));
        mx = fmaxf(mx, __shfl_xor_sync(0xffffffffu, mx, 2));
        float e[4], sum = 0.f;
#pragma unroll
        for (int r = 0; r < 4; r++) { e[r] = __expf(lg[r] - mx); sum += e[r]; }
        sum += __shfl_xor_sync(0xffffffffu, sum, 1);
        sum += __shfl_xor_sync(0xffffffffu, sum, 2);
        const float inv = 1.f / sum;

        const float2* offp = (const float2*)(offaw + (size_t)bq * 384);
        const float2* refp = (const float2*)(ref + (size_t)bq * 8);
#pragma unroll
        for (int r = 0; r < 4; r++) {
            const int s = r * 4 + j;
            const int W = c_dim[r];
            const int st = c_start[r];
            const float2 o2 = offp[h * 16 + s];
            const float2 r2 = refp[r];
            const float x = fmaf(r2.x, (float)W, o2.x) - 0.5f;
            const float y = fmaf(r2.y, (float)W, o2.y) - 0.5f;
            const float xf = floorf(x), yf = floorf(y);
            const int x0 = (int)xf, y0 = (int)yf;
            const float fx = x - xf, fy = y - yf;
            const float mx0 = ((unsigned)x0 < (unsigned)W) ? 1.f : 0.f;
            const float mx1 = ((unsigned)(x0 + 1) < (unsigned)W) ? 1.f : 0.f;
            const float my0 = ((unsigned)y0 < (unsigned)W) ? 1.f : 0.f;
            const float my1 = ((unsigned)(y0 + 1) < (unsigned)W) ? 1.f : 0.f;
            const float ww = e[r] * inv;
            const float wx0 = (1.f - fx) * mx0, wx1 = fx * mx1;
            const float wy0 = (1.f - fy) * my0, wy1 = fy * my1;
            const int xc0 = min(max(x0, 0), W - 1);
            const int xc1 = min(max(x0 + 1, 0), W - 1);
            const int yc0 = min(max(y0, 0), W - 1);
            const int yc1 = min(max(y0 + 1, 0), W - 1);
            SampRec rec;
            rec.tok[0] = st + yc0 * W + xc0;
            rec.tok[1] = st + yc0 * W + xc1;
            rec.tok[2] = st + yc1 * W + xc0;
            rec.tok[3] = st + yc1 * W + xc1;
            rec.w[0] = ww * wy0 * wx0;
            rec.w[1] = ww * wy0 * wx1;
            rec.w[2] = ww * wy1 * wx0;
            rec.w[3] = ww * wy1 * wx1;
            sm[w][h * 16 + s] = rec;
        }
    }
    __syncwarp();

    // ---- phase 2 ----
    const int item_hi = lane >> 3;
    const int sub     = lane & 7;
    const int c2      = sub >> 2;
    const int chsl    = sub & 3;

#pragma unroll 1
    for (int h = 0; h < 8; h++) {
        const __half* vbh = vhm + ((size_t)(b * 8 + h)) * (NQ * 32);
        float av[8];
#pragma unroll
        for (int k = 0; k < 8; k++) av[k] = 0.f;

#pragma unroll
        for (int ldg = 0; ldg < 8; ldg++) {
            const int it  = ldg * 4 + item_hi;
            const int t   = it >> 1;
            const int row = it & 1;
            const int i4  = row * 2 + c2;
            const int tok = sm[w][h * 16 + t].tok[i4];
            const float wt = sm[w][h * 16 + t].w[i4];
            const uint4 raw = *(const uint4*)(vbh + (size_t)tok * 32 + chsl * 8);
            const float2 f0 = __half22float2(*(const __half2*)&raw.x);
            const float2 f1 = __half22float2(*(const __half2*)&raw.y);
            const float2 f2 = __half22float2(*(const __half2*)&raw.z);
            const float2 f3 = __half22float2(*(const __half2*)&raw.w);
            av[0] = fmaf(wt, f0.x, av[0]);
            av[1] = fmaf(wt, f0.y, av[1]);
            av[2] = fmaf(wt, f1.x, av[2]);
            av[3] = fmaf(wt, f1.y, av[3]);
            av[4] = fmaf(wt, f2.x, av[4]);
            av[5] = fmaf(wt, f2.y, av[5]);
            av[6] = fmaf(wt, f3.x, av[6]);
            av[7] = fmaf(wt, f3.y, av[7]);
        }

#pragma unroll
        for (int o = 4; o <= 16; o <<= 1)
#pragma unroll
            for (int k = 0; k < 8; k++)
                av[k] += __shfl_xor_sync(0xffffffffu, av[k], o);

        if (lane < 4) {
            __half2 h0 = __floats2half2_rn(av[0], av[1]);
            __half2 h1 = __floats2half2_rn(av[2], av[3]);
            __half2 h2 = __floats2half2_rn(av[4], av[5]);
            __half2 h3 = __floats2half2_rn(av[6], av[7]);
            uint4 u = make_uint4(*(uint32_t*)&h0, *(uint32_t*)&h1,
                                 *(uint32_t*)&h2, *(uint32_t*)&h3);
            *(uint4*)(samph + (size_t)bq * 256 + h * 32 + lane * 8) = u;
        }
    }
}

// ---------------- launch ----------------
extern "C" void kernel_launch(void* const* d_in, const int* in_sizes, int n_in,
                              void* d_out, int out_size)
{
    const float* query  = (const float*)d_in[0];
    const float* refpts = (const float*)d_in[1];
    const float* value  = (const float*)d_in[2];
    const float* W_off  = (const float*)d_in[3];
    const float* b_off  = (const float*)d_in[4];
    const float* W_attn = (const float*)d_in[5];
    const float* b_attn = (const float*)d_in[6];
    const float* W_v    = (const float*)d_in[7];
    const float* b_v    = (const float*)d_in[8];
    const float* W_out  = (const float*)d_in[9];
    const float* b_out  = (const float*)d_in[10];
    float* out = (float*)d_out;

    float *offaw_s, *bcat;
    __half *qh_s, *valh_s, *vhm_s, *samph_s, *wtcat, *wtv, *wtout;
    cudaGetSymbolAddress((void**)&qh_s,    g_qh);
    cudaGetSymbolAddress((void**)&valh_s,  g_valh);
    cudaGetSymbolAddress((void**)&offaw_s, g_offaw);
    cudaGetSymbolAddress((void**)&vhm_s,   g_vhm);
    cudaGetSymbolAddress((void**)&samph_s, g_samph);
    cudaGetSymbolAddress((void**)&wtcat,   g_wtcat);
    cudaGetSymbolAddress((void**)&wtv,     g_wtv);
    cudaGetSymbolAddress((void**)&wtout,   g_wtout);
    cudaGetSymbolAddress((void**)&bcat,    g_bcat);

    static bool attr_done = false;
    if (!attr_done) {
        cudaFuncSetAttribute(hgemm<0>, cudaFuncAttributeMaxDynamicSharedMemorySize, 65536);
        cudaFuncSetAttribute(hgemm<1>, cudaFuncAttributeMaxDynamicSharedMemorySize, 65536);
        attr_done = true;
    }

    prep_weights<<<224, dim3(32, 8)>>>(W_off, W_attn, W_v, W_out,
                                       wtcat, wtv, wtout);
    concat_bias<<<1, 384>>>(b_off, b_attn, bcat);
    f2h<<<MROWS * 256 / 1024, 256>>>(query, qh_s);
    f2h<<<MROWS * 256 / 1024, 256>>>(value, valh_s);

    const int GM = MROWS / 128;   // 340
    hgemm<0><<<dim3(3, GM), 256, 65536>>>(qh_s,   wtcat, bcat, offaw_s, 384);
    hgemm<1><<<dim3(2, GM), 256, 65536>>>(valh_s, wtv,   b_v,  vhm_s,   256);

    deform_sample5<<<MROWS / 8, 256>>>(refpts, offaw_s, vhm_s, samph_s);

    hgemm<0><<<dim3(2, GM), 256, 65536>>>(samph_s, wtout, b_out, out, 256);
}

// round 9
// speedup vs baseline: 3.6573x; 1.0529x over previous
#include <cuda_runtime.h>
#include <cuda_fp16.h>
#include <cstdint>

// ---------------- problem constants ----------------
#define BS   2
#define NQ   21760
#define EMBED 256
#define NH   8
#define HD   32
#define MROWS (BS * NQ)   // 43520 = 340 * 128

__device__ __constant__ int c_dim[4]   = {128, 64, 32, 16};
__device__ __constant__ int c_start[4] = {0, 16384, 20480, 21504};

// ---------------- scratch ----------------
__device__ __align__(256) __half g_qh[MROWS * EMBED];
__device__ __align__(256) __half g_valh[MROWS * EMBED];
__device__ __align__(256) float  g_offaw[MROWS * 384];
__device__ __align__(256) __half g_vhm[MROWS * EMBED];   // [b][h][tok][32]
__device__ __align__(256) __half g_samph[MROWS * EMBED];
__device__ __align__(256) __half g_wtcat[384 * EMBED];
__device__ __align__(256) __half g_wtv[EMBED * EMBED];
__device__ __align__(256) __half g_wtout[EMBED * EMBED];
__device__ __align__(256) float  g_bcat[384];

// ---------------- helpers ----------------
__device__ __forceinline__ uint32_t smem_u32(const void* p) {
    uint32_t a;
    asm("{ .reg .u64 t; cvta.to.shared.u64 t, %1; cvt.u32.u64 %0, t; }"
        : "=r"(a) : "l"(p));
    return a;
}

#define LDSM4(r0, r1, r2, r3, addr)                                           \
    asm volatile("ldmatrix.sync.aligned.m8n8.x4.shared.b16 {%0,%1,%2,%3}, [%4];" \
                 : "=r"(r0), "=r"(r1), "=r"(r2), "=r"(r3) : "r"(addr))

#define CP16(dst, src)                                                        \
    asm volatile("cp.async.cg.shared.global [%0], [%1], 16;"                  \
                 :: "r"(dst), "l"(src) : "memory")
#define CP_COMMIT asm volatile("cp.async.commit_group;" ::: "memory")
#define CP_WAIT1  asm volatile("cp.async.wait_group 1;" ::: "memory")

__device__ __forceinline__ void mma_f16(float* d, const uint32_t* a,
                                        uint32_t b0, uint32_t b1) {
    asm volatile(
        "mma.sync.aligned.m16n8k16.row.col.f32.f16.f16.f32 "
        "{%0,%1,%2,%3}, {%4,%5,%6,%7}, {%8,%9}, {%0,%1,%2,%3};"
        : "+f"(d[0]), "+f"(d[1]), "+f"(d[2]), "+f"(d[3])
        : "r"(a[0]), "r"(a[1]), "r"(a[2]), "r"(a[3]), "r"(b0), "r"(b1));
}

// ---------------- prep: weights transpose->fp16 + bias concat, 1 launch ----
__global__ void prep_weights(const float* __restrict__ W_off,
                             const float* __restrict__ W_attn,
                             const float* __restrict__ W_v,
                             const float* __restrict__ W_out,
                             const float* __restrict__ b_off,
                             const float* __restrict__ b_attn,
                             __half* __restrict__ wtcat,
                             __half* __restrict__ wtv,
                             __half* __restrict__ wtout,
                             float* __restrict__ bcat)
{
    __shared__ float t[32][33];
    int bid = blockIdx.x;
    if (bid == 224) {   // bias concat
        const int i = threadIdx.y * 32 + threadIdx.x;          // 0..255
        bcat[i] = b_off[i];
        if (i < 128) bcat[256 + i] = b_attn[i];
        return;
    }
    const float* in;
    __half* outb;
    int cx, ry, C;
    if (bid < 64)        { in = W_off;  outb = wtcat;         cx = bid & 7; ry = bid >> 3; C = 256; }
    else if (bid < 96)   { bid -= 64;  in = W_attn; outb = wtcat + 65536; cx = bid & 3; ry = bid >> 2; C = 128; }
    else if (bid < 160)  { bid -= 96;  in = W_v;    outb = wtv;   cx = bid & 7; ry = bid >> 3; C = 256; }
    else                 { bid -= 160; in = W_out;  outb = wtout; cx = bid & 7; ry = bid >> 3; C = 256; }
    const int c0 = cx * 32, r0 = ry * 32;
    for (int i = threadIdx.y; i < 32; i += 8)
        t[i][threadIdx.x] = in[(size_t)(r0 + i) * C + c0 + threadIdx.x];
    __syncthreads();
    for (int i = threadIdx.y; i < 32; i += 8)
        outb[(size_t)(c0 + i) * 256 + r0 + threadIdx.x] = __float2half_rn(t[threadIdx.x][i]);
}

// fp32 -> fp16 for query AND value in one launch
__global__ void f2h2(const float* __restrict__ q, const float* __restrict__ v,
                     __half* __restrict__ qo, __half* __restrict__ vo)
{
    const int half = gridDim.x >> 1;
    const bool second = blockIdx.x >= half;
    const float*  in  = second ? v : q;
    __half*       out = second ? vo : qo;
    const size_t i = ((size_t)(second ? blockIdx.x - half : blockIdx.x) * 256 +
                      threadIdx.x) * 4;
    const float4 x = *(const float4*)(in + i);
    __half2 h0 = __floats2half2_rn(x.x, x.y);
    __half2 h1 = __floats2half2_rn(x.z, x.w);
    *(uint2*)(out + i) = make_uint2(*(uint32_t*)&h0, *(uint32_t*)&h1);
}

// ---------------- fp16 tensor-core GEMM body (BK=64, 3-stage cp.async) -----
// C tile 128x128 = A[M,256] @ Bt[N,256]^T + bias. Canonical SW128 layout:
// one 128B row per data row; addr = row*128 + (col ^ ((row&7)*16)).
// 4 chunks of K=64, 3 stages, ONE barrier + ONE wait per chunk.
// outmode: 0 = fp32 row-major (stride Nstr), 1 = fp16 head-major v layout.
__device__ __forceinline__ void gemm_body(
    const __half* __restrict__ A, const __half* __restrict__ Bt,
    const float* __restrict__ bias, void* __restrict__ C,
    int Nstr, int outmode, int m0, int n0, uint32_t stBase)
{
    const int tid  = threadIdx.x;
    const int lane = tid & 31;
    const int wid  = tid >> 5;
    const int wm   = wid & 1;
    const int wn   = wid >> 1;
    const int t4   = lane >> 2;
    const int tq   = lane & 3;

    // cp.async staging: thread -> (rbase=tid>>3, seg=tid&7), 4 rows apart by 32
    const int rbase = tid >> 3;
    const int seg   = tid & 7;
    const uint32_t segx = (uint32_t)((seg * 16) ^ ((rbase & 7) * 16));
    const __half* srcA = A + (size_t)(m0 + rbase) * 256 + seg * 8;
    const __half* srcB = Bt + (size_t)(n0 + rbase) * 256 + seg * 8;

    // ldmatrix addressing
    const int midx  = lane >> 3;
    const int khalf = midx >> 1;
    const int rsel  = ((midx & 1) << 3) + (lane & 7);
    const uint32_t key = (uint32_t)((lane & 7) * 16);
    uint32_t colx[4];
#pragma unroll
    for (int ks = 0; ks < 4; ks++)
        colx[ks] = (uint32_t)((2 * ks + khalf) * 16) ^ key;
    const uint32_t aRow = (uint32_t)((wm * 64 + rsel) * 128);
    const uint32_t bRow = (uint32_t)((wn * 32 + rsel) * 128) + 16384;

    float acc[4][4][4];
#pragma unroll
    for (int i = 0; i < 4; i++)
#pragma unroll
        for (int j = 0; j < 4; j++)
#pragma unroll
            for (int k = 0; k < 4; k++) acc[i][j][k] = 0.f;

    // prologue: chunks 0,1 into stages 0,1
#pragma unroll
    for (int s = 0; s < 2; s++) {
        const uint32_t st = stBase + s * 32768;
#pragma unroll
        for (int i = 0; i < 4; i++) {
            const uint32_t d = (uint32_t)((rbase + i * 32) * 128) + segx;
            CP16(st + d,         srcA + s * 64 + i * 32 * 256);
            CP16(st + 16384 + d, srcB + s * 64 + i * 32 * 256);
        }
        CP_COMMIT;
    }

#pragma unroll
    for (int c = 0; c < 4; c++) {
        CP_WAIT1;
        __syncthreads();

        if (c + 2 < 4) {
            const uint32_t st = stBase + ((c + 2) % 3) * 32768;
#pragma unroll
            for (int i = 0; i < 4; i++) {
                const uint32_t d = (uint32_t)((rbase + i * 32) * 128) + segx;
                CP16(st + d,         srcA + (c + 2) * 64 + i * 32 * 256);
                CP16(st + 16384 + d, srcB + (c + 2) * 64 + i * 32 * 256);
            }
        }
        CP_COMMIT;

        const uint32_t bufA = stBase + (c % 3) * 32768;
#pragma unroll
        for (int ks = 0; ks < 4; ks++) {
            uint32_t a[4][4], b[2][4];
#pragma unroll
            for (int mt = 0; mt < 4; mt++)
                LDSM4(a[mt][0], a[mt][1], a[mt][2], a[mt][3],
                      bufA + aRow + mt * 2048 + colx[ks]);
#pragma unroll
            for (int np = 0; np < 2; np++)
                LDSM4(b[np][0], b[np][1], b[np][2], b[np][3],
                      bufA + bRow + np * 2048 + colx[ks]);
#pragma unroll
            for (int mt = 0; mt < 4; mt++)
#pragma unroll
                for (int nt = 0; nt < 4; nt++)
                    mma_f16(acc[mt][nt], a[mt], b[nt >> 1][nt & 1],
                            b[nt >> 1][(nt & 1) + 2]);
        }
    }

    // epilogue
#pragma unroll
    for (int nt = 0; nt < 4; nt++) {
        const int col = n0 + wn * 32 + nt * 8 + tq * 2;
        const float2 bb = *(const float2*)(bias + col);
#pragma unroll
        for (int mt = 0; mt < 4; mt++) {
            const int row = m0 + wm * 64 + mt * 16 + t4;
            if (outmode == 0) {
                float2 o0 = {acc[mt][nt][0] + bb.x, acc[mt][nt][1] + bb.y};
                float2 o1 = {acc[mt][nt][2] + bb.x, acc[mt][nt][3] + bb.y};
                *(float2*)((float*)C + (size_t)row * Nstr + col) = o0;
                *(float2*)((float*)C + (size_t)(row + 8) * Nstr + col) = o1;
            } else {
                const int h = col >> 5, ch = col & 31;
                __half2 h0 = __floats2half2_rn(acc[mt][nt][0] + bb.x,
                                               acc[mt][nt][1] + bb.y);
                __half2 h1 = __floats2half2_rn(acc[mt][nt][2] + bb.x,
                                               acc[mt][nt][3] + bb.y);
                const int b0i = row / NQ,       tok0 = row - b0i * NQ;
                const int b1i = (row + 8) / NQ, tok1 = (row + 8) - b1i * NQ;
                __half* V = (__half*)C;
                *(uint32_t*)(V + (((size_t)b0i * 8 + h) * NQ + tok0) * 32 + ch) =
                    *(uint32_t*)&h0;
                *(uint32_t*)(V + (((size_t)b1i * 8 + h) * NQ + tok1) * 32 + ch) =
                    *(uint32_t*)&h1;
            }
        }
    }
}

// fused offaw + v GEMM: blocks x<3 -> offaw (N=384), x>=3 -> v (N=256, hm out)
__global__ __launch_bounds__(256, 2) void hgemm_dual(
    const __half* __restrict__ qh, const __half* __restrict__ wtcat,
    const float* __restrict__ bcat, float* __restrict__ offaw,
    const __half* __restrict__ valh, const __half* __restrict__ wtv,
    const float* __restrict__ bv, __half* __restrict__ vhm)
{
    extern __shared__ __align__(1024) uint8_t smem[];
    const uint32_t st = smem_u32(smem);
    const int m0 = blockIdx.y * 128;
    if (blockIdx.x < 3)
        gemm_body(qh, wtcat, bcat, offaw, 384, 0, m0, blockIdx.x * 128, st);
    else
        gemm_body(valh, wtv, bv, vhm, 256, 1, m0, (blockIdx.x - 3) * 128, st);
}

__global__ __launch_bounds__(256, 2) void hgemm_single(
    const __half* __restrict__ A, const __half* __restrict__ Bt,
    const float* __restrict__ bias, float* __restrict__ C)
{
    extern __shared__ __align__(1024) uint8_t smem[];
    gemm_body(A, Bt, bias, C, 256, 0, blockIdx.y * 128, blockIdx.x * 128,
              smem_u32(smem));
}

// ---------------- fused softmax + deformable sampling -----------------------
__global__ __launch_bounds__(256) void deform_sample6(
    const float* __restrict__ ref, const float* __restrict__ offaw,
    const __half* __restrict__ vhm, __half* __restrict__ samph)
{
    __shared__ uint2 sm[8][128][4];   // [warp][h*16+s][corner] = (tok, w)

    const int w    = threadIdx.x >> 5;
    const int lane = threadIdx.x & 31;
    const int bq   = blockIdx.x * 8 + w;
    const int b    = bq / NQ;

    {   // ---- phase 1 ----
        const int h = lane >> 2;
        const int j = lane & 3;
        const float* aw = offaw + (size_t)bq * 384 + 256;
        float lg[4];
#pragma unroll
        for (int r = 0; r < 4; r++) lg[r] = aw[h * 16 + r * 4 + j];
        float mx = fmaxf(fmaxf(lg[0], lg[1]), fmaxf(lg[2], lg[3]));
        mx = fmaxf(mx, __shfl_xor_sync(0xffffffffu, mx, 1));
        mx = fmaxf(mx, __shfl_xor_sync(0xffffffffu, mx, 2));
        float e[4], sum = 0.f;
#pragma unroll
        for (int r = 0; r < 4; r++) { e[r] = __expf(lg[r] - mx); sum += e[r]; }
        sum += __shfl_xor_sync(0xffffffffu, sum, 1);
        sum += __shfl_xor_sync(0xffffffffu, sum, 2);
        const float inv = 1.f / sum;

        const float2* offp = (const float2*)(offaw + (size_t)bq * 384);
        const float2* refp = (const float2*)(ref + (size_t)bq * 8);
#pragma unroll
        for (int r = 0; r < 4; r++) {
            const int s = r * 4 + j;
            const int W = c_dim[r];
            const int st = c_start[r];
            const float2 o2 = offp[h * 16 + s];
            const float2 r2 = refp[r];
            const float x = fmaf(r2.x, (float)W, o2.x) - 0.5f;
            const float y = fmaf(r2.y, (float)W, o2.y) - 0.5f;
            const float xf = floorf(x), yf = floorf(y);
            const int x0 = (int)xf, y0 = (int)yf;
            const float fx = x - xf, fy = y - yf;
            const float mx0 = ((unsigned)x0 < (unsigned)W) ? 1.f : 0.f;
            const float mx1 = ((unsigned)(x0 + 1) < (unsigned)W) ? 1.f : 0.f;
            const float my0 = ((unsigned)y0 < (unsigned)W) ? 1.f : 0.f;
            const float my1 = ((unsigned)(y0 + 1) < (unsigned)W) ? 1.f : 0.f;
            const float ww = e[r] * inv;
            const float wx0 = (1.f - fx) * mx0, wx1 = fx * mx1;
            const float wy0 = (1.f - fy) * my0, wy1 = fy * my1;
            const int xc0 = min(max(x0, 0), W - 1);
            const int xc1 = min(max(x0 + 1, 0), W - 1);
            const int yc0 = min(max(y0, 0), W - 1);
            const int yc1 = min(max(y0 + 1, 0), W - 1);
            const int t00 = st + yc0 * W + xc0;
            const int t01 = st + yc0 * W + xc1;
            const int t10 = st + yc1 * W + xc0;
            const int t11 = st + yc1 * W + xc1;
            const float w00 = ww * wy0 * wx0;
            const float w01 = ww * wy0 * wx1;
            const float w10 = ww * wy1 * wx0;
            const float w11 = ww * wy1 * wx1;
            *(uint4*)&sm[w][h * 16 + s][0] =
                make_uint4((uint32_t)t00, __float_as_uint(w00),
                           (uint32_t)t01, __float_as_uint(w01));
            *(uint4*)&sm[w][h * 16 + s][2] =
                make_uint4((uint32_t)t10, __float_as_uint(w10),
                           (uint32_t)t11, __float_as_uint(w11));
        }
    }
    __syncwarp();

    // ---- phase 2 ----
    const int item_hi = lane >> 3;
    const int sub     = lane & 7;
    const int c2      = sub >> 2;
    const int chsl    = sub & 3;

#pragma unroll 1
    for (int h = 0; h < 8; h++) {
        const __half* vbh = vhm + ((size_t)(b * 8 + h)) * (NQ * 32);
        float av[8];
#pragma unroll
        for (int k = 0; k < 8; k++) av[k] = 0.f;

#pragma unroll
        for (int ldg = 0; ldg < 8; ldg++) {
            const int it  = ldg * 4 + item_hi;
            const int t   = it >> 1;
            const int i4  = (it & 1) * 2 + c2;
            const uint2 tw = sm[w][h * 16 + t][i4];
            const int tok  = (int)tw.x;
            const float wt = __uint_as_float(tw.y);
            const uint4 raw = *(const uint4*)(vbh + (size_t)tok * 32 + chsl * 8);
            const float2 f0 = __half22float2(*(const __half2*)&raw.x);
            const float2 f1 = __half22float2(*(const __half2*)&raw.y);
            const float2 f2 = __half22float2(*(const __half2*)&raw.z);
            const float2 f3 = __half22float2(*(const __half2*)&raw.w);
            av[0] = fmaf(wt, f0.x, av[0]);
            av[1] = fmaf(wt, f0.y, av[1]);
            av[2] = fmaf(wt, f1.x, av[2]);
            av[3] = fmaf(wt, f1.y, av[3]);
            av[4] = fmaf(wt, f2.x, av[4]);
            av[5] = fmaf(wt, f2.y, av[5]);
            av[6] = fmaf(wt, f3.x, av[6]);
            av[7] = fmaf(wt, f3.y, av[7]);
        }

#pragma unroll
        for (int o = 4; o <= 16; o <<= 1)
#pragma unroll
            for (int k = 0; k < 8; k++)
                av[k] += __shfl_xor_sync(0xffffffffu, av[k], o);

        if (lane < 4) {
            __half2 h0 = __floats2half2_rn(av[0], av[1]);
            __half2 h1 = __floats2half2_rn(av[2], av[3]);
            __half2 h2 = __floats2half2_rn(av[4], av[5]);
            __half2 h3 = __floats2half2_rn(av[6], av[7]);
            uint4 u = make_uint4(*(uint32_t*)&h0, *(uint32_t*)&h1,
                                 *(uint32_t*)&h2, *(uint32_t*)&h3);
            *(uint4*)(samph + (size_t)bq * 256 + h * 32 + lane * 8) = u;
        }
    }
}

// ---------------- launch ----------------
extern "C" void kernel_launch(void* const* d_in, const int* in_sizes, int n_in,
                              void* d_out, int out_size)
{
    const float* query  = (const float*)d_in[0];
    const float* refpts = (const float*)d_in[1];
    const float* value  = (const float*)d_in[2];
    const float* W_off  = (const float*)d_in[3];
    const float* b_off  = (const float*)d_in[4];
    const float* W_attn = (const float*)d_in[5];
    const float* b_attn = (const float*)d_in[6];
    const float* W_v    = (const float*)d_in[7];
    const float* b_v    = (const float*)d_in[8];
    const float* W_out  = (const float*)d_in[9];
    const float* b_out  = (const float*)d_in[10];
    float* out = (float*)d_out;

    float *offaw_s, *bcat;
    __half *qh_s, *valh_s, *vhm_s, *samph_s, *wtcat, *wtv, *wtout;
    cudaGetSymbolAddress((void**)&qh_s,    g_qh);
    cudaGetSymbolAddress((void**)&valh_s,  g_valh);
    cudaGetSymbolAddress((void**)&offaw_s, g_offaw);
    cudaGetSymbolAddress((void**)&vhm_s,   g_vhm);
    cudaGetSymbolAddress((void**)&samph_s, g_samph);
    cudaGetSymbolAddress((void**)&wtcat,   g_wtcat);
    cudaGetSymbolAddress((void**)&wtv,     g_wtv);
    cudaGetSymbolAddress((void**)&wtout,   g_wtout);
    cudaGetSymbolAddress((void**)&bcat,    g_bcat);

    static bool attr_done = false;
    if (!attr_done) {
        cudaFuncSetAttribute(hgemm_dual,
                             cudaFuncAttributeMaxDynamicSharedMemorySize, 98304);
        cudaFuncSetAttribute(hgemm_single,
                             cudaFuncAttributeMaxDynamicSharedMemorySize, 98304);
        attr_done = true;
    }

    prep_weights<<<225, dim3(32, 8)>>>(W_off, W_attn, W_v, W_out, b_off, b_attn,
                                       wtcat, wtv, wtout, bcat);
    f2h2<<<2 * (MROWS * 256 / 1024), 256>>>(query, value, qh_s, valh_s);

    const int GM = MROWS / 128;   // 340
    hgemm_dual<<<dim3(5, GM), 256, 98304>>>(qh_s, wtcat, bcat, offaw_s,
                                            valh_s, wtv, b_v, vhm_s);

    deform_sample6<<<MROWS / 8, 256>>>(refpts, offaw_s, vhm_s, samph_s);

    hgemm_single<<<dim3(2, GM), 256, 98304>>>(samph_s, wtout, b_out, out);
}